// round 8
// baseline (speedup 1.0000x reference)
#include <cuda_runtime.h>
#include <math.h>

#define BB 16
#define LL 1024
#define DD 16
#define MM 16
#define KK 8
#define E2 66   // edge hidden = 2*(2*DIM+1)

// ---- scratch (allocation-free: __device__ globals) ----
__device__ float g_coors[2][BB*LL*3];
__device__ float g_feats[2][BB*LL*DD];
__device__ int   g_knn[BB*LL*KK];
__device__ float g_Pa[BB*LL*E2];
__device__ float g_Pb[BB*LL*E2];
__device__ int   g_wide;   // 1 if integer inputs are int64 (detected at runtime)

__device__ __forceinline__ int ld_int(const int* __restrict__ p, int i){
    return g_wide ? p[2*i] : p[i];
}

__device__ __forceinline__ float silu_f(float x){
    if (x < -30.0f) return 0.0f;
    float e = __expf(-x);
    return __fdividef(x, 1.0f + e);
}

// ---------------- detect int width: lengths[b] in [512,1024]; as int32,
// element 1 is 0 iff the buffer is int64 (high word of lengths[0]).
__global__ void k_detect(const int* __restrict__ lengths){
    if (threadIdx.x == 0 && blockIdx.x == 0)
        g_wide = (lengths[1] == 0) ? 1 : 0;
}

// ---------------- init: feats = token_emb[residues] + pos_emb ; coors = coords
__global__ void k_init(const float* __restrict__ coords, const int* __restrict__ residues,
                       const float* __restrict__ tok, const float* __restrict__ pos){
    int t = blockIdx.x*blockDim.x + threadIdx.x;
    if (t >= BB*LL) return;
    int i = t & (LL-1);
    int r = ld_int(residues, t);
#pragma unroll
    for (int c = 0; c < DD; c++)
        g_feats[0][t*DD + c] = tok[r*DD + c] + pos[i*DD + c];
    g_coors[0][t*3+0] = coords[t*3+0];
    g_coors[0][t*3+1] = coords[t*3+1];
    g_coors[0][t*3+2] = coords[t*3+2];
}

// ---------------- kNN with EXACT reference candidate semantics:
//   j == i            -> -1
//   chain adj (valid) -> 0
//   valid j           -> true squared distance (may exceed 1e5!)
//   INVALID j (>=len) -> exactly 1e5 (these CAN be selected; jax.top_k keeps them
//                        as candidates, tie-broken by ascending index)
// Selection = top-8 smallest with ascending-index tie-break. Implemented as:
// top-8 over valid j, then merge with the virtual stream {1e5 @ len, len+1, ...}.
// Ties at exactly 1e5 prefer valid j (lower index) -> '<=' in the merge.
__global__ void k_knn(int bin, const int* __restrict__ lengths){
    __shared__ float sc[LL*3];
    int b = blockIdx.x >> 4;
    int chunk = blockIdx.x & 15;
    const float* cb = &g_coors[bin][b*LL*3];
    for (int t = threadIdx.x; t < LL*3; t += blockDim.x) sc[t] = cb[t];
    __syncthreads();
    int len = ld_int(lengths, b);
    int i = chunk*64 + (int)threadIdx.x;
    int row = b*LL + i;
    float val[KK]; int idx[KK];
#pragma unroll
    for (int k = 0; k < KK; k++){ val[k] = 3.0e38f; idx[k] = i; }
    if (i < len) {
        float cx = sc[i*3], cy = sc[i*3+1], cz = sc[i*3+2];
        for (int j = 0; j < len; j++){
            float dx = cx - sc[j*3], dy = cy - sc[j*3+1], dz = cz - sc[j*3+2];
            // non-FMA form to match XLA's unfused square+sum near the 1e5 boundary
            float r = __fadd_rn(__fadd_rn(__fmul_rn(dx,dx), __fmul_rn(dy,dy)), __fmul_rn(dz,dz));
            if (j == i) r = -1.0f;
            else if (j == i-1 || j == i+1) r = 0.0f;
            if (r < val[KK-1]) {
                val[KK-1] = r; idx[KK-1] = j;
#pragma unroll
                for (int q = KK-1; q > 0; q--) {
                    if (val[q] < val[q-1]) {
                        float tv = val[q]; val[q] = val[q-1]; val[q-1] = tv;
                        int   ti = idx[q]; idx[q] = idx[q-1]; idx[q-1] = ti;
                    }
                }
            }
        }
        // merge with virtual invalid candidates (value exactly 1e5, indices len..1023)
        float mval[KK]; int midx[KK];
        int v = 0, inv = len;
#pragma unroll
        for (int k = 0; k < KK; k++) {
            if (inv >= LL || val[v] <= 1.0e5f) { mval[k] = val[v]; midx[k] = idx[v]; v++; }
            else                               { mval[k] = 1.0e5f; midx[k] = inv++; }
        }
#pragma unroll
        for (int k = 0; k < KK; k++) idx[k] = midx[k];
    }
#pragma unroll
    for (int k = 0; k < KK; k++) g_knn[row*KK + k] = idx[k];
}

// ---------------- precompute Pa = feats@W1[rows 0:16] + b1 ; Pb = feats@W1[rows 16:32]
__global__ void k_pre(int bin, const float* __restrict__ ew1, const float* __restrict__ eb1, int d){
    int t = blockIdx.x*blockDim.x + threadIdx.x;
    if (t >= BB*LL*E2) return;
    int row = t / E2, n = t - row*E2;
    const float* f = &g_feats[bin][row*DD];
    const float* w = ew1 + d*33*E2;
    float a = eb1[d*E2 + n];
    float p = 0.0f;
#pragma unroll
    for (int c = 0; c < DD; c++){
        float fc = __ldg(f + c);
        a += fc * __ldg(w + c*E2 + n);
        p += fc * __ldg(w + (DD + c)*E2 + n);
    }
    g_Pa[t] = a;
    g_Pb[t] = p;
}

// ---------------- layer: thread-per-row, straight-line reference math
__global__ void __launch_bounds__(128) k_layer(
    int bin, int d,
    const int* __restrict__ lengths,
    const float* __restrict__ ew1,
    const float* __restrict__ ew2, const float* __restrict__ eb2,
    const float* __restrict__ cw1, const float* __restrict__ cb1,
    const float* __restrict__ cw2, const float* __restrict__ cb2,
    const float* __restrict__ lng, const float* __restrict__ lnb,
    const float* __restrict__ nw1, const float* __restrict__ nb1,
    const float* __restrict__ nw2, const float* __restrict__ nb2)
{
    __shared__ float s_w1rd[E2];        // W1 row 32 (rel_dist)
    __shared__ float s_W2[E2*MM];
    __shared__ float s_b2[MM];
    __shared__ float s_cW1[MM*64];
    __shared__ float s_cb1[64];
    __shared__ float s_cW2[64];
    __shared__ float s_cb2;
    __shared__ float s_nW1[32*32];
    __shared__ float s_nb1[32];
    __shared__ float s_nW2[32*MM];
    __shared__ float s_nb2[MM];
    __shared__ float s_g[DD], s_bta[DD];

    int tid = threadIdx.x;
    for (int t = tid; t < E2; t += 128)      s_w1rd[t] = ew1[d*33*E2 + 32*E2 + t];
    for (int t = tid; t < E2*MM; t += 128)   s_W2[t]   = ew2[d*E2*MM + t];
    for (int t = tid; t < MM; t += 128)      s_b2[t]   = eb2[d*MM + t];
    for (int t = tid; t < MM*64; t += 128)   s_cW1[t]  = cw1[d*MM*64 + t];
    for (int t = tid; t < 64; t += 128)      { s_cb1[t] = cb1[d*64 + t]; s_cW2[t] = cw2[d*64 + t]; }
    if (tid == 0) s_cb2 = cb2[d];
    for (int t = tid; t < 32*32; t += 128)   s_nW1[t]  = nw1[d*32*32 + t];
    for (int t = tid; t < 32; t += 128)      s_nb1[t]  = nb1[d*32 + t];
    for (int t = tid; t < 32*MM; t += 128)   s_nW2[t]  = nw2[d*32*MM + t];
    for (int t = tid; t < MM; t += 128)      { s_nb2[t] = nb2[d*MM + t]; s_g[t] = lng[d*DD + t]; s_bta[t] = lnb[d*DD + t]; }
    __syncthreads();

    int row = blockIdx.x*128 + tid;
    if (row >= BB*LL) return;
    int b   = row >> 10;
    int i   = row & (LL-1);
    int len = ld_int(lengths, b);

    const float* coorsIn  = g_coors[bin];
    float*       coorsOut = g_coors[bin^1];
    const float* featsIn  = g_feats[bin];
    float*       featsOut = g_feats[bin^1];

    float cix = coorsIn[row*3+0], ciy = coorsIn[row*3+1], ciz = coorsIn[row*3+2];

    float m_i[MM];
#pragma unroll
    for (int c = 0; c < MM; c++) m_i[c] = 0.0f;
    float ax = 0.0f, ay = 0.0f, az = 0.0f;

    if (i < len) {
        const float* Pa = &g_Pa[(size_t)row*E2];
#pragma unroll 1
        for (int k = 0; k < KK; k++) {
            int j  = g_knn[row*KK + k];
            if (j >= len) continue;    // emask: selected invalid neighbor contributes 0
            int gj = b*LL + j;
            float dx = cix - coorsIn[gj*3+0];
            float dy = ciy - coorsIn[gj*3+1];
            float dz = ciz - coorsIn[gj*3+2];
            float rd = __fadd_rn(__fadd_rn(__fmul_rn(dx,dx), __fmul_rn(dy,dy)), __fmul_rn(dz,dz));
            const float* Pb = &g_Pb[(size_t)gj*E2];

            // edge layer 2 accumulation, layer-1 hidden streamed
            float acc[MM];
#pragma unroll
            for (int c = 0; c < MM; c++) acc[c] = s_b2[c];
#pragma unroll 2
            for (int n = 0; n < E2; n++) {
                float hval = silu_f(Pa[n] + Pb[n] + rd * s_w1rd[n]);
#pragma unroll
                for (int c = 0; c < MM; c++) acc[c] += hval * s_W2[n*MM + c];
            }
            float m[MM];
#pragma unroll
            for (int c = 0; c < MM; c++) { m[c] = silu_f(acc[c]); m_i[c] += m[c]; }

            // coors MLP: w = silu(m @ cW1 + cb1) @ cW2 + cb2 (streamed over hidden)
            float wsum = 0.0f;
#pragma unroll 2
            for (int u = 0; u < 64; u++) {
                float av = s_cb1[u];
#pragma unroll
                for (int c = 0; c < MM; c++) av += m[c] * s_cW1[c*64 + u];
                wsum += silu_f(av) * s_cW2[u];
            }
            float we = wsum + s_cb2;
            ax += we * dx; ay += we * dy; az += we * dz;
        }
    }

    coorsOut[row*3+0] = cix + ax;
    coorsOut[row*3+1] = ciy + ay;
    coorsOut[row*3+2] = ciz + az;

    // node update: LayerNorm(feats) ++ m_i -> 2-layer MLP -> residual
    float f[DD];
    float mu = 0.0f;
#pragma unroll
    for (int c = 0; c < DD; c++) { f[c] = featsIn[row*DD + c]; mu += f[c]; }
    mu *= (1.0f/16.0f);
    float var = 0.0f;
#pragma unroll
    for (int c = 0; c < DD; c++) { float dv = f[c]-mu; var += dv*dv; }
    var *= (1.0f/16.0f);
    float inv = rsqrtf(var + 1e-5f);
    float normed[DD];
#pragma unroll
    for (int c = 0; c < DD; c++) normed[c] = (f[c]-mu)*inv*s_g[c] + s_bta[c];

    float o[DD];
#pragma unroll
    for (int c = 0; c < DD; c++) o[c] = s_nb2[c];
#pragma unroll 2
    for (int u = 0; u < 32; u++) {
        float av = s_nb1[u];
#pragma unroll
        for (int t = 0; t < DD; t++) av += normed[t] * s_nW1[t*32 + u];
#pragma unroll
        for (int t = 0; t < DD; t++) av += m_i[t] * s_nW1[(DD+t)*32 + u];
        float hidv = silu_f(av);
#pragma unroll
        for (int c = 0; c < DD; c++) o[c] += hidv * s_nW2[u*MM + c];
    }
#pragma unroll
    for (int c = 0; c < DD; c++) featsOut[row*DD + c] = f[c] + o[c];
}

// ---------------- final projection: delta = feats @ final_w + final_b
__global__ void k_final(const float* __restrict__ fw, const float* __restrict__ fb, float* __restrict__ out){
    int t = blockIdx.x*blockDim.x + threadIdx.x;
    if (t >= BB*LL) return;
    const float* f = &g_feats[1][t*DD];   // after 3 layers, feats live in buffer 1
    float o0 = fb[0], o1 = fb[1], o2 = fb[2];
#pragma unroll
    for (int c2 = 0; c2 < DD; c2++){
        float fc = f[c2];
        o0 += fc * fw[c2*3+0];
        o1 += fc * fw[c2*3+1];
        o2 += fc * fw[c2*3+2];
    }
    out[t*3+0] = o0; out[t*3+1] = o1; out[t*3+2] = o2;
}

extern "C" void kernel_launch(void* const* d_in, const int* in_sizes, int n_in,
                              void* d_out, int out_size){
    // Input slot resolution. Expected (insertion) order has in_sizes[1]==16384
    // (residues). If metadata.txt is alphabetical, in_sizes[1]==192 (coors_b1).
    int I_coords=0, I_res=1, I_len=2, I_tok=3, I_pos=4,
        I_ew1=5, I_eb1=6, I_ew2=7, I_eb2=8,
        I_cw1=9, I_cb1=10, I_cw2=11, I_cb2=12,
        I_lng=13, I_lnb=14, I_nw1=15, I_nb1=16, I_nw2=17, I_nb2=18,
        I_fw=19, I_fb=20;
    if (n_in >= 21 && in_sizes[1] == 192) {
        I_coords=0; I_cb1=1; I_cb2=2; I_cw1=3; I_cw2=4;
        I_eb1=5; I_eb2=6; I_ew1=7; I_ew2=8; I_fb=9; I_fw=10; I_len=11;
        I_lnb=12; I_lng=13; I_nb1=14; I_nb2=15; I_nw1=16; I_nw2=17;
        I_pos=18; I_res=19; I_tok=20;
    }

    const float* coords   = (const float*)d_in[I_coords];
    const int*   residues = (const int*)  d_in[I_res];
    const int*   lengths  = (const int*)  d_in[I_len];
    const float* tok      = (const float*)d_in[I_tok];
    const float* pos      = (const float*)d_in[I_pos];
    const float* ew1      = (const float*)d_in[I_ew1];
    const float* eb1      = (const float*)d_in[I_eb1];
    const float* ew2      = (const float*)d_in[I_ew2];
    const float* eb2      = (const float*)d_in[I_eb2];
    const float* cw1      = (const float*)d_in[I_cw1];
    const float* cb1      = (const float*)d_in[I_cb1];
    const float* cw2      = (const float*)d_in[I_cw2];
    const float* cb2      = (const float*)d_in[I_cb2];
    const float* lng      = (const float*)d_in[I_lng];
    const float* lnb      = (const float*)d_in[I_lnb];
    const float* nw1      = (const float*)d_in[I_nw1];
    const float* nb1      = (const float*)d_in[I_nb1];
    const float* nw2      = (const float*)d_in[I_nw2];
    const float* nb2      = (const float*)d_in[I_nb2];
    const float* fw       = (const float*)d_in[I_fw];
    const float* fb       = (const float*)d_in[I_fb];
    float* out = (float*)d_out;

    k_detect<<<1, 32>>>(lengths);
    k_init<<<64, 256>>>(coords, residues, tok, pos);
    for (int dd = 0; dd < 3; dd++){
        int bin = dd & 1;
        k_knn<<<BB*16, 64>>>(bin, lengths);
        k_pre<<<(BB*LL*E2 + 255)/256, 256>>>(bin, ew1, eb1, dd);
        k_layer<<<BB*LL/128, 128>>>(bin, dd, lengths, ew1, ew2, eb2,
                                    cw1, cb1, cw2, cb2, lng, lnb,
                                    nw1, nb1, nw2, nb2);
    }
    k_final<<<64, 256>>>(fw, fb, out);
}

// round 9
// speedup vs baseline: 1.6028x; 1.6028x over previous
#include <cuda_runtime.h>
#include <math.h>

#define BB 16
#define LL 1024
#define DD 16
#define MM 16
#define KK 8
#define E2 66   // edge hidden = 2*(2*DIM+1)

// ---- scratch (allocation-free: __device__ globals) ----
__device__ float g_coors[2][BB*LL*3];
__device__ float g_feats[2][BB*LL*DD];
__device__ int   g_knn[BB*LL*KK];
__device__ float g_Pa[BB*LL*E2];
__device__ float g_Pb[BB*LL*E2];
__device__ int   g_wide;   // 1 if integer inputs are int64 (detected at runtime)

__device__ __forceinline__ int ld_int(const int* __restrict__ p, int i){
    return g_wide ? p[2*i] : p[i];
}

__device__ __forceinline__ float silu_f(float x){
    if (x < -30.0f) return 0.0f;
    float e = __expf(-x);
    return __fdividef(x, 1.0f + e);
}

// ---------------- detect int width (lengths[b] in [512,1024])
__global__ void k_detect(const int* __restrict__ lengths){
    if (threadIdx.x == 0 && blockIdx.x == 0)
        g_wide = (lengths[1] == 0) ? 1 : 0;
}

// ---------------- init: feats = token_emb[residues] + pos_emb ; coors = coords
__global__ void k_init(const float* __restrict__ coords, const int* __restrict__ residues,
                       const float* __restrict__ tok, const float* __restrict__ pos){
    int t = blockIdx.x*blockDim.x + threadIdx.x;
    if (t >= BB*LL) return;
    int i = t & (LL-1);
    int r = ld_int(residues, t);
#pragma unroll
    for (int c = 0; c < DD; c++)
        g_feats[0][t*DD + c] = tok[r*DD + c] + pos[i*DD + c];
    g_coors[0][t*3+0] = coords[t*3+0];
    g_coors[0][t*3+1] = coords[t*3+1];
    g_coors[0][t*3+2] = coords[t*3+2];
}

// ---------------- kNN with exact reference candidate semantics (see R6)
__global__ void k_knn(int bin, const int* __restrict__ lengths){
    __shared__ float sc[LL*3];
    int b = blockIdx.x >> 4;
    int chunk = blockIdx.x & 15;
    const float* cb = &g_coors[bin][b*LL*3];
    for (int t = threadIdx.x; t < LL*3; t += blockDim.x) sc[t] = cb[t];
    __syncthreads();
    int len = ld_int(lengths, b);
    int i = chunk*64 + (int)threadIdx.x;
    int row = b*LL + i;
    float val[KK]; int idx[KK];
#pragma unroll
    for (int k = 0; k < KK; k++){ val[k] = 3.0e38f; idx[k] = i; }
    if (i < len) {
        float cx = sc[i*3], cy = sc[i*3+1], cz = sc[i*3+2];
        for (int j = 0; j < len; j++){
            float dx = cx - sc[j*3], dy = cy - sc[j*3+1], dz = cz - sc[j*3+2];
            float r = __fadd_rn(__fadd_rn(__fmul_rn(dx,dx), __fmul_rn(dy,dy)), __fmul_rn(dz,dz));
            if (j == i) r = -1.0f;
            else if (j == i-1 || j == i+1) r = 0.0f;
            if (r < val[KK-1]) {
                val[KK-1] = r; idx[KK-1] = j;
#pragma unroll
                for (int q = KK-1; q > 0; q--) {
                    if (val[q] < val[q-1]) {
                        float tv = val[q]; val[q] = val[q-1]; val[q-1] = tv;
                        int   ti = idx[q]; idx[q] = idx[q-1]; idx[q-1] = ti;
                    }
                }
            }
        }
        // merge with virtual invalid candidates (value exactly 1e5, indices len..1023)
        float mval[KK]; int midx[KK];
        int v = 0, inv = len;
#pragma unroll
        for (int k = 0; k < KK; k++) {
            if (inv >= LL || val[v] <= 1.0e5f) { mval[k] = val[v]; midx[k] = idx[v]; v++; }
            else                               { mval[k] = 1.0e5f; midx[k] = inv++; }
        }
#pragma unroll
        for (int k = 0; k < KK; k++) idx[k] = midx[k];
    }
#pragma unroll
    for (int k = 0; k < KK; k++) g_knn[row*KK + k] = idx[k];
}

// ---------------- k_pre: block-tiled, smem-staged. 64 rows/block.
// Pa = feats@W1[rows 0:16] + b1 ; Pb = feats@W1[rows 16:32]
__global__ void __launch_bounds__(256) k_pre(int bin, const float* __restrict__ ew1,
                                             const float* __restrict__ eb1, int d){
    __shared__ float s_w[32*E2];
    __shared__ float s_b[E2];
    __shared__ float s_f[64*DD];
    int tid = threadIdx.x;
    const float* w = ew1 + d*33*E2;
    for (int t = tid; t < 32*E2; t += 256) s_w[t] = w[t];
    for (int t = tid; t < E2; t += 256)    s_b[t] = eb1[d*E2 + t];
    int row0 = blockIdx.x*64;
    const float* fsrc = &g_feats[bin][row0*DD];
    for (int t = tid; t < 64*DD; t += 256) s_f[t] = fsrc[t];
    __syncthreads();
    float* pa = &g_Pa[(size_t)row0*E2];
    float* pb = &g_Pb[(size_t)row0*E2];
    for (int t = tid; t < 64*E2; t += 256) {
        int r = t / E2, n = t - r*E2;
        float a = s_b[n], p = 0.0f;
        const float* fr = &s_f[r*DD];
#pragma unroll
        for (int c = 0; c < DD; c++){
            a += fr[c] * s_w[c*E2 + n];
            p += fr[c] * s_w[(DD + c)*E2 + n];
        }
        pa[t] = a;
        pb[t] = p;
    }
}

// ---------------- fused layer: warp-per-row (coalesced Pa/Pb), 8 warps/block
__global__ void __launch_bounds__(256) k_layer(
    int bin, int d,
    const int* __restrict__ lengths,
    const float* __restrict__ ew1,
    const float* __restrict__ ew2, const float* __restrict__ eb2,
    const float* __restrict__ cw1, const float* __restrict__ cb1,
    const float* __restrict__ cw2, const float* __restrict__ cb2,
    const float* __restrict__ lng, const float* __restrict__ lnb,
    const float* __restrict__ nw1, const float* __restrict__ nb1,
    const float* __restrict__ nw2, const float* __restrict__ nb2)
{
    __shared__ float s_w1rd[E2];
    __shared__ float s_W2[E2*MM];
    __shared__ float s_b2[MM];
    __shared__ float s_cW1[MM*64];
    __shared__ float s_cb1[64];
    __shared__ float s_cW2[64];
    __shared__ float s_cb2;
    __shared__ float s_nW1[32*32];
    __shared__ float s_nb1[32];
    __shared__ float s_nW2[32*MM];
    __shared__ float s_nb2[MM];
    __shared__ float s_g[DD], s_bta[DD];
    __shared__ float s_h[8][E2+2];

    int tid = threadIdx.x;
    for (int t = tid; t < E2; t += 256)      s_w1rd[t] = ew1[d*33*E2 + 32*E2 + t];
    for (int t = tid; t < E2*MM; t += 256)   s_W2[t]   = ew2[d*E2*MM + t];
    for (int t = tid; t < MM; t += 256)      s_b2[t]   = eb2[d*MM + t];
    for (int t = tid; t < MM*64; t += 256)   s_cW1[t]  = cw1[d*MM*64 + t];
    for (int t = tid; t < 64; t += 256)      { s_cb1[t] = cb1[d*64 + t]; s_cW2[t] = cw2[d*64 + t]; }
    if (tid == 0) s_cb2 = cb2[d];
    for (int t = tid; t < 32*32; t += 256)   s_nW1[t]  = nw1[d*32*32 + t];
    for (int t = tid; t < 32; t += 256)      s_nb1[t]  = nb1[d*32 + t];
    for (int t = tid; t < 32*MM; t += 256)   s_nW2[t]  = nw2[d*32*MM + t];
    for (int t = tid; t < MM; t += 256)      { s_nb2[t] = nb2[d*MM + t]; s_g[t] = lng[d*DD + t]; s_bta[t] = lnb[d*DD + t]; }
    __syncthreads();

    int w    = tid >> 5;
    int lane = tid & 31;
    int row  = blockIdx.x*8 + w;
    int b    = row >> 10;
    int i    = row & (LL-1);
    int len  = ld_int(lengths, b);
    bool valid = (i < len);

    const float* coorsIn  = g_coors[bin];
    float*       coorsOut = g_coors[bin^1];
    const float* featsIn  = g_feats[bin];
    float*       featsOut = g_feats[bin^1];

    int c    = lane & 15;
    int half = lane >> 4;

    float fcv = featsIn[row*DD + c];
    float cix = coorsIn[row*3+0], ciy = coorsIn[row*3+1], ciz = coorsIn[row*3+2];

    float m_i = 0.0f;                     // channel c (duplicated across halves)
    float ax = 0.0f, ay = 0.0f, az = 0.0f;

    if (valid) {
        const float* Pa = &g_Pa[(size_t)row*E2];
        float pa0 = Pa[lane], pa1 = Pa[lane+32];
        float pa2 = (lane < 2) ? Pa[lane+64] : 0.0f;
        float rw0 = s_w1rd[lane], rw1 = s_w1rd[lane+32];
        float rw2 = (lane < 2) ? s_w1rd[lane+64] : 0.0f;

#pragma unroll 1
        for (int k = 0; k < KK; k++) {
            int j  = g_knn[row*KK + k];
            if (j >= len) continue;       // emask: invalid selected neighbor contributes 0
            int gj = b*LL + j;
            float dx = cix - coorsIn[gj*3+0];
            float dy = ciy - coorsIn[gj*3+1];
            float dz = ciz - coorsIn[gj*3+2];
            float rd = __fadd_rn(__fadd_rn(__fmul_rn(dx,dx), __fmul_rn(dy,dy)), __fmul_rn(dz,dz));
            const float* Pb = &g_Pb[(size_t)gj*E2];

            // h = silu(Pa + Pb + rd*w_rd)  (66 values staged in smem)
            s_h[w][lane]      = silu_f(pa0 + Pb[lane]      + rd*rw0);
            s_h[w][lane+32]   = silu_f(pa1 + Pb[lane+32]   + rd*rw1);
            if (lane < 2)
                s_h[w][lane+64] = silu_f(pa2 + Pb[lane+64] + rd*rw2);
            __syncwarp();

            // m[c] = silu(b2[c] + sum_n h[n]*W2[n,c]); halves split n: [0,33) / [33,66)
            float acc = 0.0f;
            int n0 = half*33;
#pragma unroll
            for (int n = 0; n < 33; n++)
                acc += s_h[w][n0+n] * s_W2[(n0+n)*MM + c];
            acc += __shfl_xor_sync(0xffffffffu, acc, 16);
            float mval = silu_f(acc + s_b2[c]);
            m_i += mval;
            __syncwarp();

            // coors MLP: hidden units u = lane and lane+32
            float a0 = s_cb1[lane], a1 = s_cb1[lane+32];
#pragma unroll
            for (int c2 = 0; c2 < 16; c2++) {
                float mc = __shfl_sync(0xffffffffu, mval, c2);
                a0 += mc * s_cW1[c2*64 + lane];
                a1 += mc * s_cW1[c2*64 + lane + 32];
            }
            float wp = silu_f(a0) * s_cW2[lane] + silu_f(a1) * s_cW2[lane+32];
#pragma unroll
            for (int off = 16; off > 0; off >>= 1)
                wp += __shfl_xor_sync(0xffffffffu, wp, off);
            float we = wp + s_cb2;
            ax += we * dx; ay += we * dy; az += we * dz;
        }
    }

    if (lane == 0) {
        coorsOut[row*3+0] = cix + ax;
        coorsOut[row*3+1] = ciy + ay;
        coorsOut[row*3+2] = ciz + az;
    }

    // LayerNorm over the 16 feat dims (duplicated across halves)
    float s = fcv;
#pragma unroll
    for (int off = 8; off > 0; off >>= 1) s += __shfl_xor_sync(0xffffffffu, s, off);
    float mu = s * (1.0f/16.0f);
    float dv = fcv - mu;
    float v = dv*dv;
#pragma unroll
    for (int off = 8; off > 0; off >>= 1) v += __shfl_xor_sync(0xffffffffu, v, off);
    float var = v * (1.0f/16.0f);
    float normed = dv * rsqrtf(var + 1e-5f) * s_g[c] + s_bta[c];

    // nin[t]: t<16 -> normed[t], t>=16 -> m_i[t-16]
    float nin = (half == 0) ? normed : m_i;
    float a = s_nb1[lane];
#pragma unroll
    for (int t = 0; t < 32; t++) {
        float nt = __shfl_sync(0xffffffffu, nin, t);
        a += nt * s_nW1[t*32 + lane];
    }
    float hid = silu_f(a);

    // out[c] = nb2[c] + sum_u hid[u]*nW2[u,c]; halves split u
    float o = 0.0f;
    int u0 = half*16;
#pragma unroll
    for (int u = 0; u < 16; u++) {
        float hu = __shfl_sync(0xffffffffu, hid, u0 + u);
        o += hu * s_nW2[(u0+u)*MM + c];
    }
    o += __shfl_xor_sync(0xffffffffu, o, 16);
    if (half == 0)
        featsOut[row*DD + c] = fcv + o + s_nb2[c];
}

// ---------------- final projection: delta = feats @ final_w + final_b
__global__ void k_final(const float* __restrict__ fw, const float* __restrict__ fb, float* __restrict__ out){
    int t = blockIdx.x*blockDim.x + threadIdx.x;
    if (t >= BB*LL) return;
    const float* f = &g_feats[1][t*DD];   // after 3 layers, feats live in buffer 1
    float o0 = fb[0], o1 = fb[1], o2 = fb[2];
#pragma unroll
    for (int c2 = 0; c2 < DD; c2++){
        float fc = f[c2];
        o0 += fc * fw[c2*3+0];
        o1 += fc * fw[c2*3+1];
        o2 += fc * fw[c2*3+2];
    }
    out[t*3+0] = o0; out[t*3+1] = o1; out[t*3+2] = o2;
}

extern "C" void kernel_launch(void* const* d_in, const int* in_sizes, int n_in,
                              void* d_out, int out_size){
    int I_coords=0, I_res=1, I_len=2, I_tok=3, I_pos=4,
        I_ew1=5, I_eb1=6, I_ew2=7, I_eb2=8,
        I_cw1=9, I_cb1=10, I_cw2=11, I_cb2=12,
        I_lng=13, I_lnb=14, I_nw1=15, I_nb1=16, I_nw2=17, I_nb2=18,
        I_fw=19, I_fb=20;
    if (n_in >= 21 && in_sizes[1] == 192) {
        I_coords=0; I_cb1=1; I_cb2=2; I_cw1=3; I_cw2=4;
        I_eb1=5; I_eb2=6; I_ew1=7; I_ew2=8; I_fb=9; I_fw=10; I_len=11;
        I_lnb=12; I_lng=13; I_nb1=14; I_nb2=15; I_nw1=16; I_nw2=17;
        I_pos=18; I_res=19; I_tok=20;
    }

    const float* coords   = (const float*)d_in[I_coords];
    const int*   residues = (const int*)  d_in[I_res];
    const int*   lengths  = (const int*)  d_in[I_len];
    const float* tok      = (const float*)d_in[I_tok];
    const float* pos      = (const float*)d_in[I_pos];
    const float* ew1      = (const float*)d_in[I_ew1];
    const float* eb1      = (const float*)d_in[I_eb1];
    const float* ew2      = (const float*)d_in[I_ew2];
    const float* eb2      = (const float*)d_in[I_eb2];
    const float* cw1      = (const float*)d_in[I_cw1];
    const float* cb1      = (const float*)d_in[I_cb1];
    const float* cw2      = (const float*)d_in[I_cw2];
    const float* cb2      = (const float*)d_in[I_cb2];
    const float* lng      = (const float*)d_in[I_lng];
    const float* lnb      = (const float*)d_in[I_lnb];
    const float* nw1      = (const float*)d_in[I_nw1];
    const float* nb1      = (const float*)d_in[I_nb1];
    const float* nw2      = (const float*)d_in[I_nw2];
    const float* nb2      = (const float*)d_in[I_nb2];
    const float* fw       = (const float*)d_in[I_fw];
    const float* fb       = (const float*)d_in[I_fb];
    float* out = (float*)d_out;

    k_detect<<<1, 32>>>(lengths);
    k_init<<<64, 256>>>(coords, residues, tok, pos);
    for (int dd = 0; dd < 3; dd++){
        int bin = dd & 1;
        k_knn<<<BB*16, 64>>>(bin, lengths);
        k_pre<<<BB*LL/64, 256>>>(bin, ew1, eb1, dd);
        k_layer<<<BB*LL/8, 256>>>(bin, dd, lengths, ew1, ew2, eb2,
                                  cw1, cb1, cw2, cb2, lng, lnb,
                                  nw1, nb1, nw2, nb2);
    }
    k_final<<<64, 256>>>(fw, fb, out);
}

// round 10
// speedup vs baseline: 1.6838x; 1.0505x over previous
#include <cuda_runtime.h>
#include <math.h>

#define BB 16
#define LL 1024
#define DD 16
#define MM 16
#define KK 8
#define E2 66   // edge hidden = 2*(2*DIM+1)

// ---- scratch (allocation-free: __device__ globals) ----
__device__ float g_coors[2][BB*LL*3];
__device__ float g_feats[2][BB*LL*DD];
__device__ int   g_knn[BB*LL*KK];
__device__ float g_Pa[BB*LL*E2];
__device__ float g_Pb[BB*LL*E2];
__device__ int   g_wide;   // 1 if integer inputs are int64 (detected at runtime)

__device__ __forceinline__ int ld_int(const int* __restrict__ p, int i){
    return g_wide ? p[2*i] : p[i];
}

__device__ __forceinline__ float silu_f(float x){
    if (x < -30.0f) return 0.0f;
    float e = __expf(-x);
    return __fdividef(x, 1.0f + e);
}

__device__ __forceinline__ float dot4(float4 a, float4 b){
    return a.x*b.x + a.y*b.y + a.z*b.z + a.w*b.w;
}

// ---------------- detect int width (lengths[b] in [512,1024])
__global__ void k_detect(const int* __restrict__ lengths){
    if (threadIdx.x == 0 && blockIdx.x == 0)
        g_wide = (lengths[1] == 0) ? 1 : 0;
}

// ---------------- init: feats = token_emb[residues] + pos_emb ; coors = coords
__global__ void k_init(const float* __restrict__ coords, const int* __restrict__ residues,
                       const float* __restrict__ tok, const float* __restrict__ pos){
    int t = blockIdx.x*blockDim.x + threadIdx.x;
    if (t >= BB*LL) return;
    int i = t & (LL-1);
    int r = ld_int(residues, t);
#pragma unroll
    for (int c = 0; c < DD; c++)
        g_feats[0][t*DD + c] = tok[r*DD + c] + pos[i*DD + c];
    g_coors[0][t*3+0] = coords[t*3+0];
    g_coors[0][t*3+1] = coords[t*3+1];
    g_coors[0][t*3+2] = coords[t*3+2];
}

// ---------------- kNN with exact reference candidate semantics (see R6)
__global__ void k_knn(int bin, const int* __restrict__ lengths){
    __shared__ float sc[LL*3];
    int b = blockIdx.x >> 4;
    int chunk = blockIdx.x & 15;
    const float* cb = &g_coors[bin][b*LL*3];
    for (int t = threadIdx.x; t < LL*3; t += blockDim.x) sc[t] = cb[t];
    __syncthreads();
    int len = ld_int(lengths, b);
    int i = chunk*64 + (int)threadIdx.x;
    int row = b*LL + i;
    float val[KK]; int idx[KK];
#pragma unroll
    for (int k = 0; k < KK; k++){ val[k] = 3.0e38f; idx[k] = i; }
    if (i < len) {
        float cx = sc[i*3], cy = sc[i*3+1], cz = sc[i*3+2];
        for (int j = 0; j < len; j++){
            float dx = cx - sc[j*3], dy = cy - sc[j*3+1], dz = cz - sc[j*3+2];
            float r = __fadd_rn(__fadd_rn(__fmul_rn(dx,dx), __fmul_rn(dy,dy)), __fmul_rn(dz,dz));
            if (j == i) r = -1.0f;
            else if (j == i-1 || j == i+1) r = 0.0f;
            if (r < val[KK-1]) {
                val[KK-1] = r; idx[KK-1] = j;
#pragma unroll
                for (int q = KK-1; q > 0; q--) {
                    if (val[q] < val[q-1]) {
                        float tv = val[q]; val[q] = val[q-1]; val[q-1] = tv;
                        int   ti = idx[q]; idx[q] = idx[q-1]; idx[q-1] = ti;
                    }
                }
            }
        }
        // merge with virtual invalid candidates (value exactly 1e5, indices len..1023)
        float mval[KK]; int midx[KK];
        int v = 0, inv = len;
#pragma unroll
        for (int k = 0; k < KK; k++) {
            if (inv >= LL || val[v] <= 1.0e5f) { mval[k] = val[v]; midx[k] = idx[v]; v++; }
            else                               { mval[k] = 1.0e5f; midx[k] = inv++; }
        }
#pragma unroll
        for (int k = 0; k < KK; k++) idx[k] = midx[k];
    }
#pragma unroll
    for (int k = 0; k < KK; k++) g_knn[row*KK + k] = idx[k];
}

// ---------------- k_pre: 32 rows/block, transposed weights, float4 LDS
__global__ void __launch_bounds__(256) k_pre(int bin, const float* __restrict__ ew1,
                                             const float* __restrict__ eb1, int d){
    __shared__ __align__(16) float s_waT[E2][20];   // waT[n][c] = W1[c][n]      (c=0..15)
    __shared__ __align__(16) float s_wbT[E2][20];   // wbT[n][c] = W1[16+c][n]
    __shared__ __align__(16) float s_b[E2+2];
    __shared__ __align__(16) float s_f[32*DD];
    int tid = threadIdx.x;
    const float* w = ew1 + d*33*E2;
    for (int t = tid; t < 16*E2; t += 256) {
        int c = t / E2, n = t - c*E2;
        s_waT[n][c] = w[c*E2 + n];
        s_wbT[n][c] = w[(16+c)*E2 + n];
    }
    for (int t = tid; t < E2; t += 256) s_b[t] = eb1[d*E2 + t];
    int row0 = blockIdx.x*32;
    const float* fsrc = &g_feats[bin][row0*DD];
    for (int t = tid; t < 32*DD; t += 256) s_f[t] = fsrc[t];
    __syncthreads();
    float* pa = &g_Pa[(size_t)row0*E2];
    float* pb = &g_Pb[(size_t)row0*E2];
    for (int t = tid; t < 32*E2; t += 256) {
        int r = t / E2, n = t - r*E2;
        const float4* fr = (const float4*)&s_f[r*DD];
        const float4* wa = (const float4*)&s_waT[n][0];
        const float4* wb = (const float4*)&s_wbT[n][0];
        float a = s_b[n], p = 0.0f;
#pragma unroll
        for (int q = 0; q < 4; q++) {
            float4 fv = fr[q];
            float4 av = wa[q], bv = wb[q];
            a += fv.x*av.x + fv.y*av.y + fv.z*av.z + fv.w*av.w;
            p += fv.x*bv.x + fv.y*bv.y + fv.z*bv.z + fv.w*bv.w;
        }
        pa[t] = a;
        pb[t] = p;
    }
}

// ---------------- fused layer: warp-per-row, vectorized LDS.128 everywhere
__global__ void __launch_bounds__(256) k_layer(
    int bin, int d,
    const int* __restrict__ lengths,
    const float* __restrict__ ew1,
    const float* __restrict__ ew2, const float* __restrict__ eb2,
    const float* __restrict__ cw1, const float* __restrict__ cb1,
    const float* __restrict__ cw2, const float* __restrict__ cb2,
    const float* __restrict__ lng, const float* __restrict__ lnb,
    const float* __restrict__ nw1, const float* __restrict__ nb1,
    const float* __restrict__ nw2, const float* __restrict__ nb2)
{
    __shared__ __align__(16) float s_w1rd[E2+2];
    __shared__ __align__(16) float s_W2T[16][68];    // W2T[c][n] = W2[n][c], pad 68
    __shared__ __align__(16) float s_b2[MM];
    __shared__ __align__(16) float s_cW1T[64][20];   // cW1T[u][c] = cW1[c][u], pad 20
    __shared__ __align__(16) float s_cb1[64];
    __shared__ __align__(16) float s_cW2[64];
    __shared__ float s_cb2;
    __shared__ __align__(16) float s_nW1T[32][36];   // nW1T[l][t] = nW1[t][l], pad 36
    __shared__ __align__(16) float s_nb1[32];
    __shared__ __align__(16) float s_nW2T[16][36];   // nW2T[c][u] = nW2[u][c], pad 36
    __shared__ __align__(16) float s_nb2[MM];
    __shared__ __align__(16) float s_g[DD], s_bta[DD];
    __shared__ __align__(16) float s_h[8][68];
    __shared__ __align__(16) float s_m[8][16];
    __shared__ __align__(16) float s_nin[8][32];
    __shared__ __align__(16) float s_hid[8][32];

    int tid = threadIdx.x;
    for (int t = tid; t < E2; t += 256) s_w1rd[t] = ew1[d*33*E2 + 32*E2 + t];
    for (int t = tid; t < E2*MM; t += 256) {
        int n = t >> 4, c = t & 15;
        s_W2T[c][n] = ew2[d*E2*MM + t];
    }
    for (int t = tid; t < MM; t += 256) s_b2[t] = eb2[d*MM + t];
    for (int t = tid; t < MM*64; t += 256) {
        int c2 = t >> 6, u = t & 63;
        s_cW1T[u][c2] = cw1[d*MM*64 + t];
    }
    for (int t = tid; t < 64; t += 256) { s_cb1[t] = cb1[d*64 + t]; s_cW2[t] = cw2[d*64 + t]; }
    if (tid == 0) s_cb2 = cb2[d];
    for (int t = tid; t < 32*32; t += 256) {
        int tr = t >> 5, l = t & 31;
        s_nW1T[l][tr] = nw1[d*32*32 + t];
    }
    for (int t = tid; t < 32; t += 256) s_nb1[t] = nb1[d*32 + t];
    for (int t = tid; t < 32*MM; t += 256) {
        int u = t >> 4, c = t & 15;
        s_nW2T[c][u] = nw2[d*32*MM + t];
    }
    for (int t = tid; t < MM; t += 256) { s_nb2[t] = nb2[d*MM + t]; s_g[t] = lng[d*DD + t]; s_bta[t] = lnb[d*DD + t]; }
    __syncthreads();

    int w    = tid >> 5;
    int lane = tid & 31;
    int row  = blockIdx.x*8 + w;
    int b    = row >> 10;
    int i    = row & (LL-1);
    int len  = ld_int(lengths, b);
    bool valid = (i < len);

    const float* coorsIn  = g_coors[bin];
    float*       coorsOut = g_coors[bin^1];
    const float* featsIn  = g_feats[bin];
    float*       featsOut = g_feats[bin^1];

    int c    = lane & 15;
    int half = lane >> 4;

    float fcv = featsIn[row*DD + c];
    float cix = coorsIn[row*3+0], ciy = coorsIn[row*3+1], ciz = coorsIn[row*3+2];

    float m_i = 0.0f;                     // channel c (duplicated across halves)
    float ax = 0.0f, ay = 0.0f, az = 0.0f;

    if (valid) {
        const float* Pa = &g_Pa[(size_t)row*E2];
        float pa0 = Pa[lane], pa1 = Pa[lane+32];
        float pa2 = (lane < 2) ? Pa[lane+64] : 0.0f;
        float rw0 = s_w1rd[lane], rw1 = s_w1rd[lane+32];
        float rw2 = (lane < 2) ? s_w1rd[lane+64] : 0.0f;

        const float4* w2c = (const float4*)&s_W2T[c][32*half];
        const float4* hw4 = (const float4*)&s_h[w][32*half];
        const float4* cw1a = (const float4*)&s_cW1T[lane][0];
        const float4* cw1b = (const float4*)&s_cW1T[lane+32][0];
        float cw2a = s_cW2[lane], cw2b = s_cW2[lane+32];
        float cb1a = s_cb1[lane], cb1b = s_cb1[lane+32];

#pragma unroll 1
        for (int k = 0; k < KK; k++) {
            int j  = g_knn[row*KK + k];
            if (j >= len) continue;       // emask: invalid selected neighbor contributes 0
            int gj = b*LL + j;
            float dx = cix - coorsIn[gj*3+0];
            float dy = ciy - coorsIn[gj*3+1];
            float dz = ciz - coorsIn[gj*3+2];
            float rd = __fadd_rn(__fadd_rn(__fmul_rn(dx,dx), __fmul_rn(dy,dy)), __fmul_rn(dz,dz));
            const float* Pb = &g_Pb[(size_t)gj*E2];

            // h = silu(Pa + Pb + rd*w_rd)  (66 values staged in smem)
            s_h[w][lane]      = silu_f(pa0 + Pb[lane]      + rd*rw0);
            s_h[w][lane+32]   = silu_f(pa1 + Pb[lane+32]   + rd*rw1);
            if (lane < 2)
                s_h[w][lane+64] = silu_f(pa2 + Pb[lane+64] + rd*rw2);
            __syncwarp();

            // m[c] = silu(b2[c] + sum_n h[n]*W2[n][c]); half h: n in [32h,32h+32) + n=64+h
            float acc = 0.0f;
#pragma unroll
            for (int q = 0; q < 8; q++) acc += dot4(hw4[q], w2c[q]);
            acc += s_h[w][64+half] * s_W2T[c][64+half];
            acc += __shfl_xor_sync(0xffffffffu, acc, 16);
            float mval = silu_f(acc + s_b2[c]);
            m_i += mval;
            if (half == 0) s_m[w][c] = mval;
            __syncwarp();

            // coors MLP: hidden units u = lane and lane+32, m via float4 broadcast
            const float4* m4 = (const float4*)&s_m[w][0];
            float4 m0 = m4[0], m1 = m4[1], m2 = m4[2], m3 = m4[3];
            float a0 = cb1a + dot4(m0, cw1a[0]) + dot4(m1, cw1a[1]) + dot4(m2, cw1a[2]) + dot4(m3, cw1a[3]);
            float a1 = cb1b + dot4(m0, cw1b[0]) + dot4(m1, cw1b[1]) + dot4(m2, cw1b[2]) + dot4(m3, cw1b[3]);
            float wp = silu_f(a0) * cw2a + silu_f(a1) * cw2b;
#pragma unroll
            for (int off = 16; off > 0; off >>= 1)
                wp += __shfl_xor_sync(0xffffffffu, wp, off);
            float we = wp + s_cb2;
            ax += we * dx; ay += we * dy; az += we * dz;
        }
    }

    if (lane == 0) {
        coorsOut[row*3+0] = cix + ax;
        coorsOut[row*3+1] = ciy + ay;
        coorsOut[row*3+2] = ciz + az;
    }

    // LayerNorm over the 16 feat dims (duplicated across halves)
    float s = fcv;
#pragma unroll
    for (int off = 8; off > 0; off >>= 1) s += __shfl_xor_sync(0xffffffffu, s, off);
    float mu = s * (1.0f/16.0f);
    float dv = fcv - mu;
    float v = dv*dv;
#pragma unroll
    for (int off = 8; off > 0; off >>= 1) v += __shfl_xor_sync(0xffffffffu, v, off);
    float var = v * (1.0f/16.0f);
    float normed = dv * rsqrtf(var + 1e-5f) * s_g[c] + s_bta[c];

    // stage nin = [normed(16) | m_i(16)]
    if (half == 0) s_nin[w][c] = normed;
    else           s_nin[w][16+c] = m_i;
    __syncwarp();

    // hidden a[lane] = nb1[lane] + dot32(nin, nW1T[lane])
    {
        const float4* nin4 = (const float4*)&s_nin[w][0];
        const float4* w1r  = (const float4*)&s_nW1T[lane][0];
        float a = s_nb1[lane];
#pragma unroll
        for (int q = 0; q < 8; q++) a += dot4(nin4[q], w1r[q]);
        s_hid[w][lane] = silu_f(a);
    }
    __syncwarp();

    // out[c] = nb2[c] + sum_u hid[u]*nW2[u][c]; half h sums u in [16h,16h+16)
    {
        const float4* hid4 = (const float4*)&s_hid[w][16*half];
        const float4* w2r  = (const float4*)&s_nW2T[c][16*half];
        float o = 0.0f;
#pragma unroll
        for (int q = 0; q < 4; q++) o += dot4(hid4[q], w2r[q]);
        o += __shfl_xor_sync(0xffffffffu, o, 16);
        if (half == 0)
            featsOut[row*DD + c] = fcv + o + s_nb2[c];
    }
}

// ---------------- final projection: delta = feats @ final_w + final_b
__global__ void k_final(const float* __restrict__ fw, const float* __restrict__ fb, float* __restrict__ out){
    int t = blockIdx.x*blockDim.x + threadIdx.x;
    if (t >= BB*LL) return;
    const float* f = &g_feats[1][t*DD];   // after 3 layers, feats live in buffer 1
    float o0 = fb[0], o1 = fb[1], o2 = fb[2];
#pragma unroll
    for (int c2 = 0; c2 < DD; c2++){
        float fc = f[c2];
        o0 += fc * fw[c2*3+0];
        o1 += fc * fw[c2*3+1];
        o2 += fc * fw[c2*3+2];
    }
    out[t*3+0] = o0; out[t*3+1] = o1; out[t*3+2] = o2;
}

extern "C" void kernel_launch(void* const* d_in, const int* in_sizes, int n_in,
                              void* d_out, int out_size){
    int I_coords=0, I_res=1, I_len=2, I_tok=3, I_pos=4,
        I_ew1=5, I_eb1=6, I_ew2=7, I_eb2=8,
        I_cw1=9, I_cb1=10, I_cw2=11, I_cb2=12,
        I_lng=13, I_lnb=14, I_nw1=15, I_nb1=16, I_nw2=17, I_nb2=18,
        I_fw=19, I_fb=20;
    if (n_in >= 21 && in_sizes[1] == 192) {
        I_coords=0; I_cb1=1; I_cb2=2; I_cw1=3; I_cw2=4;
        I_eb1=5; I_eb2=6; I_ew1=7; I_ew2=8; I_fb=9; I_fw=10; I_len=11;
        I_lnb=12; I_lng=13; I_nb1=14; I_nb2=15; I_nw1=16; I_nw2=17;
        I_pos=18; I_res=19; I_tok=20;
    }

    const float* coords   = (const float*)d_in[I_coords];
    const int*   residues = (const int*)  d_in[I_res];
    const int*   lengths  = (const int*)  d_in[I_len];
    const float* tok      = (const float*)d_in[I_tok];
    const float* pos      = (const float*)d_in[I_pos];
    const float* ew1      = (const float*)d_in[I_ew1];
    const float* eb1      = (const float*)d_in[I_eb1];
    const float* ew2      = (const float*)d_in[I_ew2];
    const float* eb2      = (const float*)d_in[I_eb2];
    const float* cw1      = (const float*)d_in[I_cw1];
    const float* cb1      = (const float*)d_in[I_cb1];
    const float* cw2      = (const float*)d_in[I_cw2];
    const float* cb2      = (const float*)d_in[I_cb2];
    const float* lng      = (const float*)d_in[I_lng];
    const float* lnb      = (const float*)d_in[I_lnb];
    const float* nw1      = (const float*)d_in[I_nw1];
    const float* nb1      = (const float*)d_in[I_nb1];
    const float* nw2      = (const float*)d_in[I_nw2];
    const float* nb2      = (const float*)d_in[I_nb2];
    const float* fw       = (const float*)d_in[I_fw];
    const float* fb       = (const float*)d_in[I_fb];
    float* out = (float*)d_out;

    k_detect<<<1, 32>>>(lengths);
    k_init<<<64, 256>>>(coords, residues, tok, pos);
    for (int dd = 0; dd < 3; dd++){
        int bin = dd & 1;
        k_knn<<<BB*16, 64>>>(bin, lengths);
        k_pre<<<BB*LL/32, 256>>>(bin, ew1, eb1, dd);
        k_layer<<<BB*LL/8, 256>>>(bin, dd, lengths, ew1, ew2, eb2,
                                  cw1, cb1, cw2, cb2, lng, lnb,
                                  nw1, nb1, nw2, nb2);
    }
    k_final<<<64, 256>>>(fw, fb, out);
}

// round 12
// speedup vs baseline: 1.8265x; 1.0847x over previous
#include <cuda_runtime.h>
#include <math.h>

#define BB 16
#define LL 1024
#define DD 16
#define MM 16
#define KK 8
#define E2 66   // edge hidden = 2*(2*DIM+1)

// ---- scratch (allocation-free: __device__ globals) ----
__device__ float g_coors[2][BB*LL*3];
__device__ float g_feats[2][BB*LL*DD];
__device__ int   g_knn[BB*LL*KK];
__device__ float g_Pa[BB*LL*E2];
__device__ float g_Pb[BB*LL*E2];
__device__ int   g_wide;   // 1 if integer inputs are int64 (detected at runtime)

__device__ __forceinline__ int ld_int(const int* __restrict__ p, int i){
    return g_wide ? p[2*i] : p[i];
}

// branch-free silu: for x << 0, e^-x -> inf, x/inf -> -0 (correct limit)
__device__ __forceinline__ float silu_f(float x){
    return __fdividef(x, 1.0f + __expf(-x));
}

__device__ __forceinline__ float dot4(float4 a, float4 b){
    return a.x*b.x + a.y*b.y + a.z*b.z + a.w*b.w;
}

// ---------------- init (+ int-width detect): feats = tok[res] + pos ; coors = coords
__global__ void k_init(const float* __restrict__ coords, const int* __restrict__ residues,
                       const float* __restrict__ tok, const float* __restrict__ pos,
                       const int* __restrict__ lengths){
    int t = blockIdx.x*blockDim.x + threadIdx.x;
    if (t >= BB*LL) return;
    int wide = (lengths[1] == 0) ? 1 : 0;   // lengths in [512,1024]; 0 => int64 high word
    if (t == 0) g_wide = wide;
    int i = t & (LL-1);
    int r = wide ? residues[2*t] : residues[t];
#pragma unroll
    for (int c = 0; c < DD; c++)
        g_feats[0][t*DD + c] = tok[r*DD + c] + pos[i*DD + c];
    g_coors[0][t*3+0] = coords[t*3+0];
    g_coors[0][t*3+1] = coords[t*3+1];
    g_coors[0][t*3+2] = coords[t*3+2];
}

// ---------------- kNN with exact reference candidate semantics (see R6)
__global__ void k_knn(int bin, const int* __restrict__ lengths){
    __shared__ float sc[LL*3];
    int b = blockIdx.x >> 4;
    int chunk = blockIdx.x & 15;
    const float* cb = &g_coors[bin][b*LL*3];
    for (int t = threadIdx.x; t < LL*3; t += blockDim.x) sc[t] = cb[t];
    __syncthreads();
    int len = ld_int(lengths, b);
    int i = chunk*64 + (int)threadIdx.x;
    int row = b*LL + i;
    float val[KK]; int idx[KK];
#pragma unroll
    for (int k = 0; k < KK; k++){ val[k] = 3.0e38f; idx[k] = i; }
    if (i < len) {
        float cx = sc[i*3], cy = sc[i*3+1], cz = sc[i*3+2];
        for (int j = 0; j < len; j++){
            float dx = cx - sc[j*3], dy = cy - sc[j*3+1], dz = cz - sc[j*3+2];
            float r = __fadd_rn(__fadd_rn(__fmul_rn(dx,dx), __fmul_rn(dy,dy)), __fmul_rn(dz,dz));
            if (j == i) r = -1.0f;
            else if (j == i-1 || j == i+1) r = 0.0f;
            if (r < val[KK-1]) {
                val[KK-1] = r; idx[KK-1] = j;
#pragma unroll
                for (int q = KK-1; q > 0; q--) {
                    if (val[q] < val[q-1]) {
                        float tv = val[q]; val[q] = val[q-1]; val[q-1] = tv;
                        int   ti = idx[q]; idx[q] = idx[q-1]; idx[q-1] = ti;
                    }
                }
            }
        }
        // merge with virtual invalid candidates (value exactly 1e5, indices len..1023)
        float mval[KK]; int midx[KK];
        int v = 0, inv = len;
#pragma unroll
        for (int k = 0; k < KK; k++) {
            if (inv >= LL || val[v] <= 1.0e5f) { mval[k] = val[v]; midx[k] = idx[v]; v++; }
            else                               { mval[k] = 1.0e5f; midx[k] = inv++; }
        }
#pragma unroll
        for (int k = 0; k < KK; k++) idx[k] = midx[k];
    }
#pragma unroll
    for (int k = 0; k < KK; k++) g_knn[row*KK + k] = idx[k];
}

// ---------------- k_pre: 64 rows/block, transposed weights, float4 LDS
__global__ void __launch_bounds__(256) k_pre(int bin, const float* __restrict__ ew1,
                                             const float* __restrict__ eb1, int d){
    __shared__ __align__(16) float s_waT[E2][20];
    __shared__ __align__(16) float s_wbT[E2][20];
    __shared__ __align__(16) float s_b[E2+2];
    __shared__ __align__(16) float s_f[64*DD];
    int tid = threadIdx.x;
    const float* w = ew1 + d*33*E2;
    for (int t = tid; t < 16*E2; t += 256) {
        int c = t / E2, n = t - c*E2;
        s_waT[n][c] = w[c*E2 + n];
        s_wbT[n][c] = w[(16+c)*E2 + n];
    }
    for (int t = tid; t < E2; t += 256) s_b[t] = eb1[d*E2 + t];
    int row0 = blockIdx.x*64;
    const float* fsrc = &g_feats[bin][row0*DD];
    for (int t = tid; t < 64*DD; t += 256) s_f[t] = fsrc[t];
    __syncthreads();
    float* pa = &g_Pa[(size_t)row0*E2];
    float* pb = &g_Pb[(size_t)row0*E2];
    for (int t = tid; t < 64*E2; t += 256) {
        int r = t / E2, n = t - r*E2;
        const float4* fr = (const float4*)&s_f[r*DD];
        const float4* wa = (const float4*)&s_waT[n][0];
        const float4* wb = (const float4*)&s_wbT[n][0];
        float a = s_b[n], p = 0.0f;
#pragma unroll
        for (int q = 0; q < 4; q++) {
            float4 fv = fr[q];
            float4 av = wa[q], bv = wb[q];
            a += fv.x*av.x + fv.y*av.y + fv.z*av.z + fv.w*av.w;
            p += fv.x*bv.x + fv.y*bv.y + fv.z*bv.z + fv.w*bv.w;
        }
        pa[t] = a;
        pb[t] = p;
    }
}

// ---------------- fused layer: warp-per-row, EDGE-BATCHED phases
// Phase 1: h[e][66] for all 8 edges (lane-parallel over n)
// Phase 2: m[e][16] GEMM-style (lane = e*4+q, 4 channels each) -> weights read ONCE per row
// Phase 3: coors MLP (lane (e,q) handles u = 4t+q), w[e] masked, coordinate update
// Phase 4: LayerNorm + node MLP (as before)
#define HSTR 76   // s_h edge stride (bank-staggered, float4-aligned)
#define MSTR 20   // s_m edge stride
__global__ void __launch_bounds__(256) k_layer(
    int bin, int d,
    const int* __restrict__ lengths,
    const float* __restrict__ ew1,
    const float* __restrict__ ew2, const float* __restrict__ eb2,
    const float* __restrict__ cw1, const float* __restrict__ cb1,
    const float* __restrict__ cw2, const float* __restrict__ cb2,
    const float* __restrict__ lng, const float* __restrict__ lnb,
    const float* __restrict__ nw1, const float* __restrict__ nb1,
    const float* __restrict__ nw2, const float* __restrict__ nb2)
{
    __shared__ __align__(16) float s_w1rd[E2+2];
    __shared__ __align__(16) float s_W2[E2*MM];      // [n][c] original layout
    __shared__ __align__(16) float s_b2[MM];
    __shared__ __align__(16) float s_cW1T[64][20];   // cW1T[u][c] = cW1[c][u]
    __shared__ __align__(16) float s_cb1[64];
    __shared__ __align__(16) float s_cW2[64];
    __shared__ float s_cb2;
    __shared__ __align__(16) float s_nW1T[32][36];   // nW1T[l][t] = nW1[t][l]
    __shared__ __align__(16) float s_nb1[32];
    __shared__ __align__(16) float s_nW2T[16][36];   // nW2T[c][u] = nW2[u][c]
    __shared__ __align__(16) float s_nb2[MM];
    __shared__ __align__(16) float s_g[DD], s_bta[DD];
    __shared__ __align__(16) float s_h[8][KK*HSTR];  // per warp: 8 edges x 66 (stride 76)
    __shared__ __align__(16) float s_m[8][KK*MSTR];  // per warp: 8 edges x 16 (stride 20)
    __shared__ __align__(16) float s_nin[8][32];
    __shared__ __align__(16) float s_hid[8][32];

    int tid = threadIdx.x;
    for (int t = tid; t < E2; t += 256) s_w1rd[t] = ew1[d*33*E2 + 32*E2 + t];
    for (int t = tid; t < E2*MM; t += 256) s_W2[t] = ew2[d*E2*MM + t];
    for (int t = tid; t < MM; t += 256) s_b2[t] = eb2[d*MM + t];
    for (int t = tid; t < MM*64; t += 256) {
        int c2 = t >> 6, u = t & 63;
        s_cW1T[u][c2] = cw1[d*MM*64 + t];
    }
    for (int t = tid; t < 64; t += 256) { s_cb1[t] = cb1[d*64 + t]; s_cW2[t] = cw2[d*64 + t]; }
    if (tid == 0) s_cb2 = cb2[d];
    for (int t = tid; t < 32*32; t += 256) {
        int tr = t >> 5, l = t & 31;
        s_nW1T[l][tr] = nw1[d*32*32 + t];
    }
    for (int t = tid; t < 32; t += 256) s_nb1[t] = nb1[d*32 + t];
    for (int t = tid; t < 32*MM; t += 256) {
        int u = t >> 4, c = t & 15;
        s_nW2T[c][u] = nw2[d*32*MM + t];
    }
    for (int t = tid; t < MM; t += 256) { s_nb2[t] = nb2[d*MM + t]; s_g[t] = lng[d*DD + t]; s_bta[t] = lnb[d*DD + t]; }
    __syncthreads();

    int w    = tid >> 5;
    int lane = tid & 31;
    int row  = blockIdx.x*8 + w;
    int b    = row >> 10;
    int i    = row & (LL-1);
    int len  = ld_int(lengths, b);
    bool vrow = (i < len);

    const float* coorsIn  = g_coors[bin];
    float*       coorsOut = g_coors[bin^1];
    const float* featsIn  = g_feats[bin];
    float*       featsOut = g_feats[bin^1];

    int c    = lane & 15;
    int half = lane >> 4;
    int e    = lane >> 2;   // edge owned in phases 2/3
    int q    = lane & 3;

    float fcv = featsIn[row*DD + c];
    float cix = coorsIn[row*3+0], ciy = coorsIn[row*3+1], ciz = coorsIn[row*3+2];

    float ax = 0.0f, ay = 0.0f, az = 0.0f;
    float4 mi4 = make_float4(0.f, 0.f, 0.f, 0.f);   // m_i[4q..4q+3] (valid on all lanes after reduce)

    float* hW = &s_h[w][0];
    float* mW = &s_m[w][0];

    if (vrow) {
        // ---- edge setup: lane kk = lane&7 owns edge kk (duplicated across upper lanes)
        int kk = lane & 7;
        int j  = g_knn[row*KK + kk];
        float maskf = (j < len) ? 1.0f : 0.0f;
        int gj = b*LL + j;
        float dxk = cix - coorsIn[gj*3+0];
        float dyk = ciy - coorsIn[gj*3+1];
        float dzk = ciz - coorsIn[gj*3+2];
        float rdk = __fadd_rn(__fadd_rn(__fmul_rn(dxk,dxk), __fmul_rn(dyk,dyk)), __fmul_rn(dzk,dzk));

        // ---- phase 1: h for all 8 edges
        const float* Pa = &g_Pa[(size_t)row*E2];
        float pa0 = Pa[lane], pa1 = Pa[lane+32];
        float pa2 = (lane < 2) ? Pa[lane+64] : 0.0f;
        float rw0 = s_w1rd[lane], rw1 = s_w1rd[lane+32];
        float rw2 = (lane < 2) ? s_w1rd[lane+64] : 0.0f;
#pragma unroll
        for (int ee = 0; ee < KK; ee++) {
            float rd = __shfl_sync(0xffffffffu, rdk, ee);
            int   gje = __shfl_sync(0xffffffffu, gj,  ee);
            const float* Pb = &g_Pb[(size_t)gje*E2];
            hW[ee*HSTR + lane]    = silu_f(pa0 + Pb[lane]    + rd*rw0);
            hW[ee*HSTR + lane+32] = silu_f(pa1 + Pb[lane+32] + rd*rw1);
            if (lane < 2)
                hW[ee*HSTR + lane+64] = silu_f(pa2 + Pb[lane+64] + rd*rw2);
        }
        __syncwarp();

        // ---- phase 2: m[e][4q..4q+3] = silu(h[e] @ W2 + b2) * mask
        {
            const float4* w2q = (const float4*)s_W2;      // [n*4 + q]
            const float4* h4  = (const float4*)&hW[e*HSTR];
            float4 b4 = ((const float4*)s_b2)[q];
            float4 acc = b4;
#pragma unroll
            for (int g = 0; g < 16; g++) {
                float4 hh = h4[g];
                float4 w0 = w2q[(4*g+0)*4 + q];
                float4 w1 = w2q[(4*g+1)*4 + q];
                float4 w2v = w2q[(4*g+2)*4 + q];
                float4 w3 = w2q[(4*g+3)*4 + q];
                acc.x += hh.x*w0.x + hh.y*w1.x + hh.z*w2v.x + hh.w*w3.x;
                acc.y += hh.x*w0.y + hh.y*w1.y + hh.z*w2v.y + hh.w*w3.y;
                acc.z += hh.x*w0.z + hh.y*w1.z + hh.z*w2v.z + hh.w*w3.z;
                acc.w += hh.x*w0.w + hh.y*w1.w + hh.z*w2v.w + hh.w*w3.w;
            }
            float h64 = hW[e*HSTR + 64], h65 = hW[e*HSTR + 65];
            float4 w64 = w2q[64*4 + q], w65 = w2q[65*4 + q];
            acc.x += h64*w64.x + h65*w65.x;
            acc.y += h64*w64.y + h65*w65.y;
            acc.z += h64*w64.z + h65*w65.z;
            acc.w += h64*w64.w + h65*w65.w;

            float me = __shfl_sync(0xffffffffu, maskf, e);   // lane e owns edge e's mask
            float4 mv;
            mv.x = silu_f(acc.x) * me;
            mv.y = silu_f(acc.y) * me;
            mv.z = silu_f(acc.z) * me;
            mv.w = silu_f(acc.w) * me;
            *(float4*)&mW[e*MSTR + 4*q] = mv;

            // m_i reduce across the 8 edge groups
            mi4 = mv;
#pragma unroll
            for (int off = 4; off <= 16; off <<= 1) {
                mi4.x += __shfl_xor_sync(0xffffffffu, mi4.x, off);
                mi4.y += __shfl_xor_sync(0xffffffffu, mi4.y, off);
                mi4.z += __shfl_xor_sync(0xffffffffu, mi4.z, off);
                mi4.w += __shfl_xor_sync(0xffffffffu, mi4.w, off);
            }
        }
        __syncwarp();

        // ---- phase 3: coors MLP; lane (e,q) handles u = 4t+q for its edge
        {
            const float4* m4 = (const float4*)&mW[e*MSTR];
            float4 mr0 = m4[0], mr1 = m4[1], mr2 = m4[2], mr3 = m4[3];
            const float4* cw1T4 = (const float4*)s_cW1T;   // row u at u*5
            float wacc = 0.0f;
#pragma unroll
            for (int t = 0; t < 16; t++) {
                int u = 4*t + q;
                float a = s_cb1[u]
                        + dot4(mr0, cw1T4[u*5+0]) + dot4(mr1, cw1T4[u*5+1])
                        + dot4(mr2, cw1T4[u*5+2]) + dot4(mr3, cw1T4[u*5+3]);
                wacc += silu_f(a) * s_cW2[u];
            }
            wacc += __shfl_xor_sync(0xffffffffu, wacc, 1);
            wacc += __shfl_xor_sync(0xffffffffu, wacc, 2);
            // edge kk's w lives (reduced) at lane 4*kk
            float wk = (__shfl_sync(0xffffffffu, wacc, 4*kk) + s_cb2) * maskf;
            float tx = wk*dxk, ty = wk*dyk, tz = wk*dzk;
#pragma unroll
            for (int off = 1; off <= 4; off <<= 1) {
                tx += __shfl_xor_sync(0xffffffffu, tx, off);
                ty += __shfl_xor_sync(0xffffffffu, ty, off);
                tz += __shfl_xor_sync(0xffffffffu, tz, off);
            }
            ax = tx; ay = ty; az = tz;
        }
    }

    if (lane == 0) {
        coorsOut[row*3+0] = cix + ax;
        coorsOut[row*3+1] = ciy + ay;
        coorsOut[row*3+2] = ciz + az;
    }

    // ---- phase 4: LayerNorm + node MLP (all rows)
    float s = fcv;
#pragma unroll
    for (int off = 8; off > 0; off >>= 1) s += __shfl_xor_sync(0xffffffffu, s, off);
    float mu = s * (1.0f/16.0f);
    float dv = fcv - mu;
    float v = dv*dv;
#pragma unroll
    for (int off = 8; off > 0; off >>= 1) v += __shfl_xor_sync(0xffffffffu, v, off);
    float var = v * (1.0f/16.0f);
    float normed = dv * rsqrtf(var + 1e-5f) * s_g[c] + s_bta[c];

    if (half == 0) s_nin[w][c] = normed;
    if (lane < 4)  *(float4*)&s_nin[w][16 + 4*q] = mi4;   // zeros if !vrow
    __syncwarp();

    {
        const float4* nin4 = (const float4*)&s_nin[w][0];
        const float4* w1r  = (const float4*)&s_nW1T[lane][0];
        float a = s_nb1[lane];
#pragma unroll
        for (int g = 0; g < 8; g++) a += dot4(nin4[g], w1r[g]);
        s_hid[w][lane] = silu_f(a);
    }
    __syncwarp();

    {
        const float4* hid4 = (const float4*)&s_hid[w][16*half];
        const float4* w2r  = (const float4*)&s_nW2T[c][16*half];
        float o = 0.0f;
#pragma unroll
        for (int g2 = 0; g2 < 4; g2++) o += dot4(hid4[g2], w2r[g2]);
        o += __shfl_xor_sync(0xffffffffu, o, 16);
        if (half == 0)
            featsOut[row*DD + c] = fcv + o + s_nb2[c];
    }
}

// ---------------- final projection: delta = feats @ final_w + final_b
__global__ void k_final(const float* __restrict__ fw, const float* __restrict__ fb, float* __restrict__ out){
    int t = blockIdx.x*blockDim.x + threadIdx.x;
    if (t >= BB*LL) return;
    const float* f = &g_feats[1][t*DD];   // after 3 layers, feats live in buffer 1
    float o0 = fb[0], o1 = fb[1], o2 = fb[2];
#pragma unroll
    for (int c2 = 0; c2 < DD; c2++){
        float fc = f[c2];
        o0 += fc * fw[c2*3+0];
        o1 += fc * fw[c2*3+1];
        o2 += fc * fw[c2*3+2];
    }
    out[t*3+0] = o0; out[t*3+1] = o1; out[t*3+2] = o2;
}

extern "C" void kernel_launch(void* const* d_in, const int* in_sizes, int n_in,
                              void* d_out, int out_size){
    int I_coords=0, I_res=1, I_len=2, I_tok=3, I_pos=4,
        I_ew1=5, I_eb1=6, I_ew2=7, I_eb2=8,
        I_cw1=9, I_cb1=10, I_cw2=11, I_cb2=12,
        I_lng=13, I_lnb=14, I_nw1=15, I_nb1=16, I_nw2=17, I_nb2=18,
        I_fw=19, I_fb=20;
    if (n_in >= 21 && in_sizes[1] == 192) {
        I_coords=0; I_cb1=1; I_cb2=2; I_cw1=3; I_cw2=4;
        I_eb1=5; I_eb2=6; I_ew1=7; I_ew2=8; I_fb=9; I_fw=10; I_len=11;
        I_lnb=12; I_lng=13; I_nb1=14; I_nb2=15; I_nw1=16; I_nw2=17;
        I_pos=18; I_res=19; I_tok=20;
    }

    const float* coords   = (const float*)d_in[I_coords];
    const int*   residues = (const int*)  d_in[I_res];
    const int*   lengths  = (const int*)  d_in[I_len];
    const float* tok      = (const float*)d_in[I_tok];
    const float* pos      = (const float*)d_in[I_pos];
    const float* ew1      = (const float*)d_in[I_ew1];
    const float* eb1      = (const float*)d_in[I_eb1];
    const float* ew2      = (const float*)d_in[I_ew2];
    const float* eb2      = (const float*)d_in[I_eb2];
    const float* cw1      = (const float*)d_in[I_cw1];
    const float* cb1      = (const float*)d_in[I_cb1];
    const float* cw2      = (const float*)d_in[I_cw2];
    const float* cb2      = (const float*)d_in[I_cb2];
    const float* lng      = (const float*)d_in[I_lng];
    const float* lnb      = (const float*)d_in[I_lnb];
    const float* nw1      = (const float*)d_in[I_nw1];
    const float* nb1      = (const float*)d_in[I_nb1];
    const float* nw2      = (const float*)d_in[I_nw2];
    const float* nb2      = (const float*)d_in[I_nb2];
    const float* fw       = (const float*)d_in[I_fw];
    const float* fb       = (const float*)d_in[I_fb];
    float* out = (float*)d_out;

    k_init<<<64, 256>>>(coords, residues, tok, pos, lengths);
    for (int dd = 0; dd < 3; dd++){
        int bin = dd & 1;
        k_knn<<<BB*16, 64>>>(bin, lengths);
        k_pre<<<BB*LL/64, 256>>>(bin, ew1, eb1, dd);
        k_layer<<<BB*LL/8, 256>>>(bin, dd, lengths, ew1, ew2, eb2,
                                  cw1, cb1, cw2, cb2, lng, lnb,
                                  nw1, nb1, nw2, nb2);
    }
    k_final<<<64, 256>>>(fw, fb, out);
}

// round 13
// speedup vs baseline: 2.5532x; 1.3979x over previous
#include <cuda_runtime.h>
#include <math.h>

#define BB 16
#define LL 1024
#define DD 16
#define MM 16
#define KK 8
#define E2 66   // edge hidden = 2*(2*DIM+1)

typedef unsigned long long ull;

// ---- scratch (allocation-free: __device__ globals) ----
__device__ float g_coors[2][BB*LL*3];
__device__ float g_feats[2][BB*LL*DD];
__device__ int   g_knn[BB*LL*KK];
__device__ float g_Pa[BB*LL*E2];
__device__ float g_Pb[BB*LL*E2];
__device__ int   g_wide;   // 1 if integer inputs are int64 (detected at runtime)

__device__ __forceinline__ int ld_int(const int* __restrict__ p, int i){
    return g_wide ? p[2*i] : p[i];
}

// branch-free silu: for x << 0, e^-x -> inf, x/inf -> -0 (correct limit)
__device__ __forceinline__ float silu_f(float x){
    return __fdividef(x, 1.0f + __expf(-x));
}

__device__ __forceinline__ float dot4(float4 a, float4 b){
    return a.x*b.x + a.y*b.y + a.z*b.z + a.w*b.w;
}

// ---- packed f32x2 helpers (FFMA2: only reachable via PTX) ----
__device__ __forceinline__ void fma2(ull& d, ull a, ull b){
    asm("fma.rn.f32x2 %0, %1, %2, %0;" : "+l"(d) : "l"(a), "l"(b));
}
__device__ __forceinline__ ull pack2(float x, float y){
    ull r; asm("mov.b64 %0, {%1, %2};" : "=l"(r) : "f"(x), "f"(y)); return r;
}
__device__ __forceinline__ float2 unpack2(ull v){
    float2 r; asm("mov.b64 {%0, %1}, %2;" : "=f"(r.x), "=f"(r.y) : "l"(v)); return r;
}

// ---------------- init (+ int-width detect)
__global__ void k_init(const float* __restrict__ coords, const int* __restrict__ residues,
                       const float* __restrict__ tok, const float* __restrict__ pos,
                       const int* __restrict__ lengths){
    int t = blockIdx.x*blockDim.x + threadIdx.x;
    if (t >= BB*LL) return;
    int wide = (lengths[1] == 0) ? 1 : 0;   // lengths in [512,1024]; 0 => int64 high word
    if (t == 0) g_wide = wide;
    int i = t & (LL-1);
    int r = wide ? residues[2*t] : residues[t];
#pragma unroll
    for (int c = 0; c < DD; c++)
        g_feats[0][t*DD + c] = tok[r*DD + c] + pos[i*DD + c];
    g_coors[0][t*3+0] = coords[t*3+0];
    g_coors[0][t*3+1] = coords[t*3+1];
    g_coors[0][t*3+2] = coords[t*3+2];
}

// top-8 insertion (strict '<' keeps ascending-j stability within a scan)
__device__ __forceinline__ void ins8(float (&val)[KK], int (&idx)[KK], float r, int j){
    if (r < val[KK-1]) {
        val[KK-1] = r; idx[KK-1] = j;
#pragma unroll
        for (int q = KK-1; q > 0; q--) {
            if (val[q] < val[q-1]) {
                float tv = val[q]; val[q] = val[q-1]; val[q-1] = tv;
                int   ti = idx[q]; idx[q] = idx[q-1]; idx[q-1] = ti;
            }
        }
    }
}

// ---------------- fused kNN (blocks 0..255) + Pa/Pb precompute (blocks 256..511)
// kNN: 64 rows/block, 4 threads per row (j split in quarters of 256), merged
// with lower-quarter-preferred ties (== ascending-j tie-break), then the
// virtual-invalid 1e5 merge (reference candidate semantics, see R6).
__global__ void __launch_bounds__(256) k_knnpre(int bin, const int* __restrict__ lengths,
                                                const float* __restrict__ ew1,
                                                const float* __restrict__ eb1, int d){
    int tid = threadIdx.x;
    if (blockIdx.x < 256) {
        __shared__ __align__(16) float4 sc4[LL];
        __shared__ float s_mv[4*64*KK];
        __shared__ int   s_mi[4*64*KK];
        int b = blockIdx.x >> 4;
        int chunk = blockIdx.x & 15;
        const float* cb = &g_coors[bin][b*LL*3];
        for (int t = tid; t < LL; t += 256)
            sc4[t] = make_float4(cb[t*3], cb[t*3+1], cb[t*3+2], 0.0f);
        __syncthreads();
        int len = ld_int(lengths, b);
        int r  = tid & 63;
        int q  = tid >> 6;
        int i  = chunk*64 + r;

        float val[KK]; int idx[KK];
#pragma unroll
        for (int k = 0; k < KK; k++){ val[k] = 3.0e38f; idx[k] = i; }

        if (i < len) {
            float4 ci = sc4[i];
            int lo = q*256;
            int hi = min(lo + 256, len);
            int m1 = min(hi, max(lo, i-1));     // end of pure region 1
            int m2 = max(lo, min(hi, i+2));     // start of pure region 3
            for (int j = lo; j < m1; j++) {
                float4 cj = sc4[j];
                float dx = ci.x - cj.x, dy = ci.y - cj.y, dz = ci.z - cj.z;
                float rr = __fadd_rn(__fadd_rn(__fmul_rn(dx,dx), __fmul_rn(dy,dy)), __fmul_rn(dz,dz));
                ins8(val, idx, rr, j);
            }
            for (int j = m1; j < min(hi, i+2); j++) {   // specials: j in {i-1, i, i+1}
                float rr = (j == i) ? -1.0f : 0.0f;
                ins8(val, idx, rr, j);
            }
            for (int j = m2; j < hi; j++) {
                float4 cj = sc4[j];
                float dx = ci.x - cj.x, dy = ci.y - cj.y, dz = ci.z - cj.z;
                float rr = __fadd_rn(__fadd_rn(__fmul_rn(dx,dx), __fmul_rn(dy,dy)), __fmul_rn(dz,dz));
                ins8(val, idx, rr, j);
            }
        }
#pragma unroll
        for (int k = 0; k < KK; k++) {
            s_mv[(q*64 + r)*KK + k] = val[k];
            s_mi[(q*64 + r)*KK + k] = idx[k];
        }
        __syncthreads();

        if (tid < 64) {
            int rr = tid;
            int ii2 = chunk*64 + rr;
            int row = b*LL + ii2;
            float vv[KK]; int vi[KK];
            int p0=0, p1=0, p2=0, p3=0;
#pragma unroll
            for (int k = 0; k < KK; k++) {
                float v0 = s_mv[(0*64+rr)*KK + p0];
                float v1 = s_mv[(1*64+rr)*KK + p1];
                float v2 = s_mv[(2*64+rr)*KK + p2];
                float v3 = s_mv[(3*64+rr)*KK + p3];
                int best = 0; float bv = v0;
                if (v1 < bv) { bv = v1; best = 1; }
                if (v2 < bv) { bv = v2; best = 2; }
                if (v3 < bv) { bv = v3; best = 3; }
                int bp = (best==0) ? p0 : (best==1) ? p1 : (best==2) ? p2 : p3;
                vv[k] = bv;
                vi[k] = s_mi[(best*64+rr)*KK + bp];
                p0 += (best==0); p1 += (best==1); p2 += (best==2); p3 += (best==3);
            }
            if (ii2 < len) {
                // merge with virtual invalid candidates (value exactly 1e5, idx len..1023)
                int v = 0, inv = len;
                int fi[KK];
#pragma unroll
                for (int k = 0; k < KK; k++) {
                    if (inv >= LL || vv[v] <= 1.0e5f) { fi[k] = vi[v]; v++; }
                    else                              { fi[k] = inv++; }
                }
#pragma unroll
                for (int k = 0; k < KK; k++) vi[k] = fi[k];
            }
#pragma unroll
            for (int k = 0; k < KK; k++) g_knn[row*KK + k] = vi[k];
        }
    } else {
        // ---- pre: Pa = feats@W1[rows 0:16]+b1 ; Pb = feats@W1[rows 16:32]
        __shared__ __align__(16) float s_waT[E2][20];
        __shared__ __align__(16) float s_wbT[E2][20];
        __shared__ __align__(16) float s_b[E2+2];
        __shared__ __align__(16) float s_f[64*DD];
        const float* w = ew1 + d*33*E2;
        for (int t = tid; t < 16*E2; t += 256) {
            int c = t / E2, n = t - c*E2;
            s_waT[n][c] = w[c*E2 + n];
            s_wbT[n][c] = w[(16+c)*E2 + n];
        }
        for (int t = tid; t < E2; t += 256) s_b[t] = eb1[d*E2 + t];
        int row0 = (blockIdx.x - 256)*64;
        const float* fsrc = &g_feats[bin][row0*DD];
        for (int t = tid; t < 64*DD; t += 256) s_f[t] = fsrc[t];
        __syncthreads();
        float* pa = &g_Pa[(size_t)row0*E2];
        float* pb = &g_Pb[(size_t)row0*E2];
        for (int t = tid; t < 64*E2; t += 256) {
            int r = t / E2, n = t - r*E2;
            const float4* fr = (const float4*)&s_f[r*DD];
            const float4* wa = (const float4*)&s_waT[n][0];
            const float4* wb = (const float4*)&s_wbT[n][0];
            float a = s_b[n], p = 0.0f;
#pragma unroll
            for (int qq = 0; qq < 4; qq++) {
                float4 fv = fr[qq];
                float4 av = wa[qq], bv = wb[qq];
                a += fv.x*av.x + fv.y*av.y + fv.z*av.z + fv.w*av.w;
                p += fv.x*bv.x + fv.y*bv.y + fv.z*bv.z + fv.w*bv.w;
            }
            pa[t] = a;
            pb[t] = p;
        }
    }
}

// ---------------- fused layer: warp-per-row, edge-batched, f32x2 inner math
#define HSTR 76
#define MSTR 20
__global__ void __launch_bounds__(256) k_layer(
    int bin, int d,
    const int* __restrict__ lengths,
    const float* __restrict__ ew1,
    const float* __restrict__ ew2, const float* __restrict__ eb2,
    const float* __restrict__ cw1, const float* __restrict__ cb1,
    const float* __restrict__ cw2, const float* __restrict__ cb2,
    const float* __restrict__ lng, const float* __restrict__ lnb,
    const float* __restrict__ nw1, const float* __restrict__ nb1,
    const float* __restrict__ nw2, const float* __restrict__ nb2)
{
    __shared__ __align__(16) float s_w1rd[E2+2];
    __shared__ __align__(16) float s_W2[E2*MM];      // [n][c]
    __shared__ __align__(16) float s_b2[MM];
    __shared__ __align__(16) float s_cW1T[64][20];   // [u][c]
    __shared__ __align__(16) float s_cb1[64];
    __shared__ __align__(16) float s_cW2[64];
    __shared__ float s_cb2;
    __shared__ __align__(16) float s_nW1T[32][36];   // [l][t]
    __shared__ __align__(16) float s_nb1[32];
    __shared__ __align__(16) float s_nW2T[16][36];   // [c][u]
    __shared__ __align__(16) float s_nb2[MM];
    __shared__ __align__(16) float s_g[DD], s_bta[DD];
    __shared__ __align__(16) float s_h[8][KK*HSTR];
    __shared__ __align__(16) float s_m[8][KK*MSTR];
    __shared__ __align__(16) float s_nin[8][32];
    __shared__ __align__(16) float s_hid[8][32];

    int tid = threadIdx.x;
    for (int t = tid; t < E2; t += 256) s_w1rd[t] = ew1[d*33*E2 + 32*E2 + t];
    for (int t = tid; t < E2*MM; t += 256) s_W2[t] = ew2[d*E2*MM + t];
    for (int t = tid; t < MM; t += 256) s_b2[t] = eb2[d*MM + t];
    for (int t = tid; t < MM*64; t += 256) {
        int c2 = t >> 6, u = t & 63;
        s_cW1T[u][c2] = cw1[d*MM*64 + t];
    }
    for (int t = tid; t < 64; t += 256) { s_cb1[t] = cb1[d*64 + t]; s_cW2[t] = cw2[d*64 + t]; }
    if (tid == 0) s_cb2 = cb2[d];
    for (int t = tid; t < 32*32; t += 256) {
        int tr = t >> 5, l = t & 31;
        s_nW1T[l][tr] = nw1[d*32*32 + t];
    }
    for (int t = tid; t < 32; t += 256) s_nb1[t] = nb1[d*32 + t];
    for (int t = tid; t < 32*MM; t += 256) {
        int u = t >> 4, c = t & 15;
        s_nW2T[c][u] = nw2[d*32*MM + t];
    }
    for (int t = tid; t < MM; t += 256) { s_nb2[t] = nb2[d*MM + t]; s_g[t] = lng[d*DD + t]; s_bta[t] = lnb[d*DD + t]; }
    __syncthreads();

    int w    = tid >> 5;
    int lane = tid & 31;
    int row  = blockIdx.x*8 + w;
    int b    = row >> 10;
    int i    = row & (LL-1);
    int len  = ld_int(lengths, b);
    bool vrow = (i < len);

    const float* coorsIn  = g_coors[bin];
    float*       coorsOut = g_coors[bin^1];
    const float* featsIn  = g_feats[bin];
    float*       featsOut = g_feats[bin^1];

    int c    = lane & 15;
    int half = lane >> 4;
    int e    = lane >> 2;
    int q    = lane & 3;

    float fcv = featsIn[row*DD + c];
    float cix = coorsIn[row*3+0], ciy = coorsIn[row*3+1], ciz = coorsIn[row*3+2];

    float ax = 0.0f, ay = 0.0f, az = 0.0f;
    float4 mi4 = make_float4(0.f, 0.f, 0.f, 0.f);

    float* hW = &s_h[w][0];
    float* mW = &s_m[w][0];

    if (vrow) {
        int kk = lane & 7;
        int j  = g_knn[row*KK + kk];
        float maskf = (j < len) ? 1.0f : 0.0f;
        int gj = b*LL + j;
        float dxk = cix - coorsIn[gj*3+0];
        float dyk = ciy - coorsIn[gj*3+1];
        float dzk = ciz - coorsIn[gj*3+2];
        float rdk = __fadd_rn(__fadd_rn(__fmul_rn(dxk,dxk), __fmul_rn(dyk,dyk)), __fmul_rn(dzk,dzk));

        // ---- phase 1: h for all 8 edges
        const float* Pa = &g_Pa[(size_t)row*E2];
        float pa0 = Pa[lane], pa1 = Pa[lane+32];
        float pa2 = (lane < 2) ? Pa[lane+64] : 0.0f;
        float rw0 = s_w1rd[lane], rw1 = s_w1rd[lane+32];
        float rw2 = (lane < 2) ? s_w1rd[lane+64] : 0.0f;
#pragma unroll
        for (int ee = 0; ee < KK; ee++) {
            float rd = __shfl_sync(0xffffffffu, rdk, ee);
            int   gje = __shfl_sync(0xffffffffu, gj,  ee);
            const float* Pb = &g_Pb[(size_t)gje*E2];
            hW[ee*HSTR + lane]    = silu_f(pa0 + Pb[lane]    + rd*rw0);
            hW[ee*HSTR + lane+32] = silu_f(pa1 + Pb[lane+32] + rd*rw1);
            if (lane < 2)
                hW[ee*HSTR + lane+64] = silu_f(pa2 + Pb[lane+64] + rd*rw2);
        }
        __syncwarp();

        // ---- phase 2: m[e][4q..4q+3] = silu(h[e] @ W2 + b2) * mask  (f32x2)
        {
            const ulonglong2* w2p = (const ulonglong2*)s_W2;   // row n at n*4, lane chunk +q
            const float4* h4 = (const float4*)&hW[e*HSTR];
            ull acc01 = pack2(s_b2[4*q],   s_b2[4*q+1]);
            ull acc23 = pack2(s_b2[4*q+2], s_b2[4*q+3]);
#pragma unroll
            for (int g = 0; g < 16; g++) {
                float4 hh = h4[g];
                ulonglong2 wv0 = w2p[(4*g+0)*4 + q];
                ull hp = pack2(hh.x, hh.x);
                fma2(acc01, hp, wv0.x); fma2(acc23, hp, wv0.y);
                ulonglong2 wv1 = w2p[(4*g+1)*4 + q];
                hp = pack2(hh.y, hh.y);
                fma2(acc01, hp, wv1.x); fma2(acc23, hp, wv1.y);
                ulonglong2 wv2 = w2p[(4*g+2)*4 + q];
                hp = pack2(hh.z, hh.z);
                fma2(acc01, hp, wv2.x); fma2(acc23, hp, wv2.y);
                ulonglong2 wv3 = w2p[(4*g+3)*4 + q];
                hp = pack2(hh.w, hh.w);
                fma2(acc01, hp, wv3.x); fma2(acc23, hp, wv3.y);
            }
            float h64 = hW[e*HSTR + 64], h65 = hW[e*HSTR + 65];
            ulonglong2 wv64 = w2p[64*4 + q];
            ull hp = pack2(h64, h64);
            fma2(acc01, hp, wv64.x); fma2(acc23, hp, wv64.y);
            ulonglong2 wv65 = w2p[65*4 + q];
            hp = pack2(h65, h65);
            fma2(acc01, hp, wv65.x); fma2(acc23, hp, wv65.y);

            float2 a01 = unpack2(acc01), a23 = unpack2(acc23);
            float me = __shfl_sync(0xffffffffu, maskf, e);
            float4 mv;
            mv.x = silu_f(a01.x) * me;
            mv.y = silu_f(a01.y) * me;
            mv.z = silu_f(a23.x) * me;
            mv.w = silu_f(a23.y) * me;
            *(float4*)&mW[e*MSTR + 4*q] = mv;

            mi4 = mv;
#pragma unroll
            for (int off = 4; off <= 16; off <<= 1) {
                mi4.x += __shfl_xor_sync(0xffffffffu, mi4.x, off);
                mi4.y += __shfl_xor_sync(0xffffffffu, mi4.y, off);
                mi4.z += __shfl_xor_sync(0xffffffffu, mi4.z, off);
                mi4.w += __shfl_xor_sync(0xffffffffu, mi4.w, off);
            }
        }
        __syncwarp();

        // ---- phase 3: coors MLP (f32x2); lane (e,q) handles u = 4t+q
        {
            const float4* m4 = (const float4*)&mW[e*MSTR];
            float4 mr0 = m4[0], mr1 = m4[1], mr2 = m4[2], mr3 = m4[3];
            ull mp0 = pack2(mr0.x, mr0.y), mp1 = pack2(mr0.z, mr0.w);
            ull mp2 = pack2(mr1.x, mr1.y), mp3 = pack2(mr1.z, mr1.w);
            ull mp4 = pack2(mr2.x, mr2.y), mp5 = pack2(mr2.z, mr2.w);
            ull mp6 = pack2(mr3.x, mr3.y), mp7 = pack2(mr3.z, mr3.w);
            const ulonglong2* cwp = (const ulonglong2*)s_cW1T;   // row u at u*5
            float wacc = 0.0f;
#pragma unroll
            for (int t = 0; t < 16; t++) {
                int u = 4*t + q;
                ulonglong2 w0 = cwp[u*5+0];
                ulonglong2 w1 = cwp[u*5+1];
                ull s01 = pack2(s_cb1[u], 0.0f);
                fma2(s01, mp0, w0.x); fma2(s01, mp1, w0.y);
                fma2(s01, mp2, w1.x); fma2(s01, mp3, w1.y);
                ulonglong2 w2v = cwp[u*5+2];
                ulonglong2 w3 = cwp[u*5+3];
                fma2(s01, mp4, w2v.x); fma2(s01, mp5, w2v.y);
                fma2(s01, mp6, w3.x);  fma2(s01, mp7, w3.y);
                float2 sv = unpack2(s01);
                wacc += silu_f(sv.x + sv.y) * s_cW2[u];
            }
            wacc += __shfl_xor_sync(0xffffffffu, wacc, 1);
            wacc += __shfl_xor_sync(0xffffffffu, wacc, 2);
            float wk = (__shfl_sync(0xffffffffu, wacc, 4*kk) + s_cb2) * maskf;
            float tx = wk*dxk, ty = wk*dyk, tz = wk*dzk;
#pragma unroll
            for (int off = 1; off <= 4; off <<= 1) {
                tx += __shfl_xor_sync(0xffffffffu, tx, off);
                ty += __shfl_xor_sync(0xffffffffu, ty, off);
                tz += __shfl_xor_sync(0xffffffffu, tz, off);
            }
            ax = tx; ay = ty; az = tz;
        }
    }

    if (lane == 0) {
        coorsOut[row*3+0] = cix + ax;
        coorsOut[row*3+1] = ciy + ay;
        coorsOut[row*3+2] = ciz + az;
    }

    // ---- phase 4: LayerNorm + node MLP (all rows)
    float s = fcv;
#pragma unroll
    for (int off = 8; off > 0; off >>= 1) s += __shfl_xor_sync(0xffffffffu, s, off);
    float mu = s * (1.0f/16.0f);
    float dv = fcv - mu;
    float v = dv*dv;
#pragma unroll
    for (int off = 8; off > 0; off >>= 1) v += __shfl_xor_sync(0xffffffffu, v, off);
    float var = v * (1.0f/16.0f);
    float normed = dv * rsqrtf(var + 1e-5f) * s_g[c] + s_bta[c];

    if (half == 0) s_nin[w][c] = normed;
    if (lane < 4)  *(float4*)&s_nin[w][16 + 4*q] = mi4;
    __syncwarp();

    {
        const ulonglong2* nin2 = (const ulonglong2*)&s_nin[w][0];
        const ulonglong2* w1r2 = (const ulonglong2*)&s_nW1T[lane][0];
        ull acc = pack2(s_nb1[lane], 0.0f);
#pragma unroll
        for (int g = 0; g < 8; g++) {
            ulonglong2 nv = nin2[g];
            ulonglong2 wv = w1r2[g];
            fma2(acc, nv.x, wv.x);
            fma2(acc, nv.y, wv.y);
        }
        float2 av = unpack2(acc);
        s_hid[w][lane] = silu_f(av.x + av.y);
    }
    __syncwarp();

    {
        const float4* hid4 = (const float4*)&s_hid[w][16*half];
        const float4* w2r  = (const float4*)&s_nW2T[c][16*half];
        float o = 0.0f;
#pragma unroll
        for (int g2 = 0; g2 < 4; g2++) o += dot4(hid4[g2], w2r[g2]);
        o += __shfl_xor_sync(0xffffffffu, o, 16);
        if (half == 0)
            featsOut[row*DD + c] = fcv + o + s_nb2[c];
    }
}

// ---------------- final projection: delta = feats @ final_w + final_b
__global__ void k_final(const float* __restrict__ fw, const float* __restrict__ fb, float* __restrict__ out){
    int t = blockIdx.x*blockDim.x + threadIdx.x;
    if (t >= BB*LL) return;
    const float* f = &g_feats[1][t*DD];   // after 3 layers, feats live in buffer 1
    float o0 = fb[0], o1 = fb[1], o2 = fb[2];
#pragma unroll
    for (int c2 = 0; c2 < DD; c2++){
        float fc = f[c2];
        o0 += fc * fw[c2*3+0];
        o1 += fc * fw[c2*3+1];
        o2 += fc * fw[c2*3+2];
    }
    out[t*3+0] = o0; out[t*3+1] = o1; out[t*3+2] = o2;
}

extern "C" void kernel_launch(void* const* d_in, const int* in_sizes, int n_in,
                              void* d_out, int out_size){
    int I_coords=0, I_res=1, I_len=2, I_tok=3, I_pos=4,
        I_ew1=5, I_eb1=6, I_ew2=7, I_eb2=8,
        I_cw1=9, I_cb1=10, I_cw2=11, I_cb2=12,
        I_lng=13, I_lnb=14, I_nw1=15, I_nb1=16, I_nw2=17, I_nb2=18,
        I_fw=19, I_fb=20;
    if (n_in >= 21 && in_sizes[1] == 192) {
        I_coords=0; I_cb1=1; I_cb2=2; I_cw1=3; I_cw2=4;
        I_eb1=5; I_eb2=6; I_ew1=7; I_ew2=8; I_fb=9; I_fw=10; I_len=11;
        I_lnb=12; I_lng=13; I_nb1=14; I_nb2=15; I_nw1=16; I_nw2=17;
        I_pos=18; I_res=19; I_tok=20;
    }

    const float* coords   = (const float*)d_in[I_coords];
    const int*   residues = (const int*)  d_in[I_res];
    const int*   lengths  = (const int*)  d_in[I_len];
    const float* tok      = (const float*)d_in[I_tok];
    const float* pos      = (const float*)d_in[I_pos];
    const float* ew1      = (const float*)d_in[I_ew1];
    const float* eb1      = (const float*)d_in[I_eb1];
    const float* ew2      = (const float*)d_in[I_ew2];
    const float* eb2      = (const float*)d_in[I_eb2];
    const float* cw1      = (const float*)d_in[I_cw1];
    const float* cb1      = (const float*)d_in[I_cb1];
    const float* cw2      = (const float*)d_in[I_cw2];
    const float* cb2      = (const float*)d_in[I_cb2];
    const float* lng      = (const float*)d_in[I_lng];
    const float* lnb      = (const float*)d_in[I_lnb];
    const float* nw1      = (const float*)d_in[I_nw1];
    const float* nb1      = (const float*)d_in[I_nb1];
    const float* nw2      = (const float*)d_in[I_nw2];
    const float* nb2      = (const float*)d_in[I_nb2];
    const float* fw       = (const float*)d_in[I_fw];
    const float* fb       = (const float*)d_in[I_fb];
    float* out = (float*)d_out;

    k_init<<<64, 256>>>(coords, residues, tok, pos, lengths);
    for (int dd = 0; dd < 3; dd++){
        int bin = dd & 1;
        k_knnpre<<<512, 256>>>(bin, lengths, ew1, eb1, dd);
        k_layer<<<BB*LL/8, 256>>>(bin, dd, lengths, ew1, ew2, eb2,
                                  cw1, cb1, cw2, cb2, lng, lnb,
                                  nw1, nb1, nw2, nb2);
    }
    k_final<<<64, 256>>>(fw, fb, out);
}

// round 14
// speedup vs baseline: 2.6804x; 1.0498x over previous
#include <cuda_runtime.h>
#include <math.h>

#define BB 16
#define LL 1024
#define DD 16
#define MM 16
#define KK 8
#define E2 66   // edge hidden = 2*(2*DIM+1)

typedef unsigned long long ull;

// ---- scratch (allocation-free: __device__ globals) ----
__device__ float g_coors[2][BB*LL*3];
__device__ float g_feats[2][BB*LL*DD];
__device__ int   g_knn[BB*LL*KK];
__device__ float g_Pa[BB*LL*E2];
__device__ float g_Pb[BB*LL*E2];
__device__ int   g_wide;   // 1 if integer inputs are int64 (detected at runtime)

__device__ __forceinline__ int ld_int(const int* __restrict__ p, int i){
    return g_wide ? p[2*i] : p[i];
}

// branch-free silu: for x << 0, e^-x -> inf, x/inf -> -0 (correct limit)
__device__ __forceinline__ float silu_f(float x){
    return __fdividef(x, 1.0f + __expf(-x));
}

__device__ __forceinline__ float dot4(float4 a, float4 b){
    return a.x*b.x + a.y*b.y + a.z*b.z + a.w*b.w;
}

// ---- packed f32x2 helpers (FFMA2: only reachable via PTX) ----
__device__ __forceinline__ void fma2(ull& d, ull a, ull b){
    asm("fma.rn.f32x2 %0, %1, %2, %0;" : "+l"(d) : "l"(a), "l"(b));
}
__device__ __forceinline__ ull pack2(float x, float y){
    ull r; asm("mov.b64 %0, {%1, %2};" : "=l"(r) : "f"(x), "f"(y)); return r;
}
__device__ __forceinline__ float2 unpack2(ull v){
    float2 r; asm("mov.b64 {%0, %1}, %2;" : "=f"(r.x), "=f"(r.y) : "l"(v)); return r;
}

// ---------------- init (+ int-width detect)
__global__ void k_init(const float* __restrict__ coords, const int* __restrict__ residues,
                       const float* __restrict__ tok, const float* __restrict__ pos,
                       const int* __restrict__ lengths){
    int t = blockIdx.x*blockDim.x + threadIdx.x;
    if (t >= BB*LL) return;
    int wide = (lengths[1] == 0) ? 1 : 0;   // lengths in [512,1024]; 0 => int64 high word
    if (t == 0) g_wide = wide;
    int i = t & (LL-1);
    int r = wide ? residues[2*t] : residues[t];
#pragma unroll
    for (int c = 0; c < DD; c++)
        g_feats[0][t*DD + c] = tok[r*DD + c] + pos[i*DD + c];
    g_coors[0][t*3+0] = coords[t*3+0];
    g_coors[0][t*3+1] = coords[t*3+1];
    g_coors[0][t*3+2] = coords[t*3+2];
}

// top-8 insertion (strict '<' keeps ascending-j stability within a scan)
__device__ __forceinline__ void ins8(float (&val)[KK], int (&idx)[KK], float r, int j){
    if (r < val[KK-1]) {
        val[KK-1] = r; idx[KK-1] = j;
#pragma unroll
        for (int q = KK-1; q > 0; q--) {
            if (val[q] < val[q-1]) {
                float tv = val[q]; val[q] = val[q-1]; val[q-1] = tv;
                int   ti = idx[q]; idx[q] = idx[q-1]; idx[q-1] = ti;
            }
        }
    }
}

#define NS 8      // j-splits per row
#define RB 32     // rows per knn block
#define MS 9      // merge smem stride (coprime with 32 -> conflict-free)

// ---------------- fused kNN (blocks 0..511) + Pa/Pb precompute (blocks 512..767)
// kNN: 32 rows/block, 8 threads/row (j in chunks of 128), merged with
// lower-chunk-preferred strict '<' ties (== ascending-j tie-break), then the
// virtual-invalid 1e5 merge (reference candidate semantics, see R6).
__global__ void __launch_bounds__(256) k_knnpre(int bin, const int* __restrict__ lengths,
                                                const float* __restrict__ ew1,
                                                const float* __restrict__ eb1, int d){
    int tid = threadIdx.x;
    if (blockIdx.x < 512) {
        __shared__ __align__(16) float4 sc4[LL];
        __shared__ float s_mv[NS*RB*MS];
        __shared__ int   s_mi[NS*RB*MS];
        int b = blockIdx.x >> 5;
        int chunk = blockIdx.x & 31;
        const float* cb = &g_coors[bin][b*LL*3];
        for (int t = tid; t < LL; t += 256)
            sc4[t] = make_float4(cb[t*3], cb[t*3+1], cb[t*3+2], 0.0f);
        __syncthreads();
        int len = ld_int(lengths, b);
        int r  = tid & (RB-1);
        int q  = tid >> 5;          // 0..7
        int i  = chunk*RB + r;

        float val[KK]; int idx[KK];
#pragma unroll
        for (int k = 0; k < KK; k++){ val[k] = 3.0e38f; idx[k] = i; }

        if (i < len) {
            float4 ci = sc4[i];
            int lo = q*128;
            int hi = min(lo + 128, len);
            int m1 = min(hi, max(lo, i-1));     // end of pure region 1
            int m2 = max(lo, min(hi, i+2));     // start of pure region 3
            for (int j = lo; j < m1; j++) {
                float4 cj = sc4[j];
                float dx = ci.x - cj.x, dy = ci.y - cj.y, dz = ci.z - cj.z;
                float rr = __fadd_rn(__fadd_rn(__fmul_rn(dx,dx), __fmul_rn(dy,dy)), __fmul_rn(dz,dz));
                ins8(val, idx, rr, j);
            }
            for (int j = m1; j < min(hi, i+2); j++) {   // specials: j in {i-1, i, i+1}
                float rr = (j == i) ? -1.0f : 0.0f;
                ins8(val, idx, rr, j);
            }
            for (int j = m2; j < hi; j++) {
                float4 cj = sc4[j];
                float dx = ci.x - cj.x, dy = ci.y - cj.y, dz = ci.z - cj.z;
                float rr = __fadd_rn(__fadd_rn(__fmul_rn(dx,dx), __fmul_rn(dy,dy)), __fmul_rn(dz,dz));
                ins8(val, idx, rr, j);
            }
        }
#pragma unroll
        for (int k = 0; k < KK; k++) {
            s_mv[(q*RB + r)*MS + k] = val[k];
            s_mi[(q*RB + r)*MS + k] = idx[k];
        }
        __syncthreads();

        if (tid < RB) {
            int rr = tid;
            int ii2 = chunk*RB + rr;
            int row = b*LL + ii2;
            float vv[KK]; int vi[KK];
            int p[NS];
#pragma unroll
            for (int qq = 0; qq < NS; qq++) p[qq] = 0;
#pragma unroll
            for (int k = 0; k < KK; k++) {
                int best = 0;
                float bv = s_mv[(0*RB+rr)*MS + p[0]];
#pragma unroll
                for (int qq = 1; qq < NS; qq++) {
                    float vq = s_mv[(qq*RB+rr)*MS + p[qq]];
                    if (vq < bv) { bv = vq; best = qq; }
                }
                vv[k] = bv;
#pragma unroll
                for (int qq = 0; qq < NS; qq++)
                    if (best == qq) { vi[k] = s_mi[(qq*RB+rr)*MS + p[qq]]; p[qq]++; }
            }
            if (ii2 < len) {
                // merge with virtual invalid candidates (value exactly 1e5, idx len..1023)
                int v = 0, inv = len;
                int fi[KK];
#pragma unroll
                for (int k = 0; k < KK; k++) {
                    if (inv >= LL || vv[v] <= 1.0e5f) { fi[k] = vi[v]; v++; }
                    else                              { fi[k] = inv++; }
                }
#pragma unroll
                for (int k = 0; k < KK; k++) vi[k] = fi[k];
            }
#pragma unroll
            for (int k = 0; k < KK; k++) g_knn[row*KK + k] = vi[k];
        }
    } else {
        // ---- pre: Pa = feats@W1[rows 0:16]+b1 ; Pb = feats@W1[rows 16:32]
        __shared__ __align__(16) float s_waT[E2][20];
        __shared__ __align__(16) float s_wbT[E2][20];
        __shared__ __align__(16) float s_b[E2+2];
        __shared__ __align__(16) float s_f[64*DD];
        const float* w = ew1 + d*33*E2;
        for (int t = tid; t < 16*E2; t += 256) {
            int c = t / E2, n = t - c*E2;
            s_waT[n][c] = w[c*E2 + n];
            s_wbT[n][c] = w[(16+c)*E2 + n];
        }
        for (int t = tid; t < E2; t += 256) s_b[t] = eb1[d*E2 + t];
        int row0 = (blockIdx.x - 512)*64;
        const float* fsrc = &g_feats[bin][row0*DD];
        for (int t = tid; t < 64*DD; t += 256) s_f[t] = fsrc[t];
        __syncthreads();
        float* pa = &g_Pa[(size_t)row0*E2];
        float* pb = &g_Pb[(size_t)row0*E2];
        for (int t = tid; t < 64*E2; t += 256) {
            int r = t / E2, n = t - r*E2;
            const float4* fr = (const float4*)&s_f[r*DD];
            const float4* wa = (const float4*)&s_waT[n][0];
            const float4* wb = (const float4*)&s_wbT[n][0];
            float a = s_b[n], p = 0.0f;
#pragma unroll
            for (int qq = 0; qq < 4; qq++) {
                float4 fv = fr[qq];
                float4 av = wa[qq], bv = wb[qq];
                a += fv.x*av.x + fv.y*av.y + fv.z*av.z + fv.w*av.w;
                p += fv.x*bv.x + fv.y*bv.y + fv.z*bv.z + fv.w*bv.w;
            }
            pa[t] = a;
            pb[t] = p;
        }
    }
}

// ---------------- fused layer: warp-per-row, edge-batched, f32x2 inner math
#define HSTR 76
#define MSTR 20
__global__ void __launch_bounds__(256) k_layer(
    int bin, int d,
    const int* __restrict__ lengths,
    const float* __restrict__ ew1,
    const float* __restrict__ ew2, const float* __restrict__ eb2,
    const float* __restrict__ cw1, const float* __restrict__ cb1,
    const float* __restrict__ cw2, const float* __restrict__ cb2,
    const float* __restrict__ lng, const float* __restrict__ lnb,
    const float* __restrict__ nw1, const float* __restrict__ nb1,
    const float* __restrict__ nw2, const float* __restrict__ nb2)
{
    __shared__ __align__(16) float s_w1rd[E2+2];
    __shared__ __align__(16) float s_W2[E2*MM];      // [n][c]
    __shared__ __align__(16) float s_b2[MM];
    __shared__ __align__(16) float s_cW1T[64][20];   // [u][0:16)=cW1T, [16]=cb1, [17]=cW2
    __shared__ float s_cb2;
    __shared__ __align__(16) float s_nW1T[32][36];   // [l][t]
    __shared__ __align__(16) float s_nb1[32];
    __shared__ __align__(16) float s_nW2T[16][36];   // [c][u]
    __shared__ __align__(16) float s_nb2[MM];
    __shared__ __align__(16) float s_g[DD], s_bta[DD];
    __shared__ __align__(16) float s_h[8][KK*HSTR];
    __shared__ __align__(16) float s_m[8][KK*MSTR];
    __shared__ __align__(16) float s_nin[8][32];
    __shared__ __align__(16) float s_hid[8][32];

    int tid = threadIdx.x;
    for (int t = tid; t < E2; t += 256) s_w1rd[t] = ew1[d*33*E2 + 32*E2 + t];
    for (int t = tid; t < E2*MM; t += 256) s_W2[t] = ew2[d*E2*MM + t];
    for (int t = tid; t < MM; t += 256) s_b2[t] = eb2[d*MM + t];
    for (int t = tid; t < MM*64; t += 256) {
        int c2 = t >> 6, u = t & 63;
        s_cW1T[u][c2] = cw1[d*MM*64 + t];
    }
    for (int t = tid; t < 64; t += 256) { s_cW1T[t][16] = cb1[d*64 + t]; s_cW1T[t][17] = cw2[d*64 + t]; }
    if (tid == 0) s_cb2 = cb2[d];
    for (int t = tid; t < 32*32; t += 256) {
        int tr = t >> 5, l = t & 31;
        s_nW1T[l][tr] = nw1[d*32*32 + t];
    }
    for (int t = tid; t < 32; t += 256) s_nb1[t] = nb1[d*32 + t];
    for (int t = tid; t < 32*MM; t += 256) {
        int u = t >> 4, c = t & 15;
        s_nW2T[c][u] = nw2[d*32*MM + t];
    }
    for (int t = tid; t < MM; t += 256) { s_nb2[t] = nb2[d*MM + t]; s_g[t] = lng[d*DD + t]; s_bta[t] = lnb[d*DD + t]; }
    __syncthreads();

    int w    = tid >> 5;
    int lane = tid & 31;
    int row  = blockIdx.x*8 + w;
    int b    = row >> 10;
    int i    = row & (LL-1);
    int len  = ld_int(lengths, b);
    bool vrow = (i < len);

    const float* coorsIn  = g_coors[bin];
    float*       coorsOut = g_coors[bin^1];
    const float* featsIn  = g_feats[bin];
    float*       featsOut = g_feats[bin^1];

    int c    = lane & 15;
    int half = lane >> 4;
    int e    = lane >> 2;
    int q    = lane & 3;

    float fcv = featsIn[row*DD + c];
    float cix = coorsIn[row*3+0], ciy = coorsIn[row*3+1], ciz = coorsIn[row*3+2];

    float ax = 0.0f, ay = 0.0f, az = 0.0f;
    float4 mi4 = make_float4(0.f, 0.f, 0.f, 0.f);

    float* hW = &s_h[w][0];
    float* mW = &s_m[w][0];

    if (vrow) {
        int kk = lane & 7;
        int j  = g_knn[row*KK + kk];
        float maskf = (j < len) ? 1.0f : 0.0f;
        int gj = b*LL + j;
        float dxk = cix - coorsIn[gj*3+0];
        float dyk = ciy - coorsIn[gj*3+1];
        float dzk = ciz - coorsIn[gj*3+2];
        float rdk = __fadd_rn(__fadd_rn(__fmul_rn(dxk,dxk), __fmul_rn(dyk,dyk)), __fmul_rn(dzk,dzk));

        // ---- phase 1: h for all 8 edges
        const float* Pa = &g_Pa[(size_t)row*E2];
        float pa0 = Pa[lane], pa1 = Pa[lane+32];
        float pa2 = (lane < 2) ? Pa[lane+64] : 0.0f;
        float rw0 = s_w1rd[lane], rw1 = s_w1rd[lane+32];
        float rw2 = (lane < 2) ? s_w1rd[lane+64] : 0.0f;
#pragma unroll
        for (int ee = 0; ee < KK; ee++) {
            float rd = __shfl_sync(0xffffffffu, rdk, ee);
            int   gje = __shfl_sync(0xffffffffu, gj,  ee);
            const float* Pb = &g_Pb[(size_t)gje*E2];
            hW[ee*HSTR + lane]    = silu_f(pa0 + Pb[lane]    + rd*rw0);
            hW[ee*HSTR + lane+32] = silu_f(pa1 + Pb[lane+32] + rd*rw1);
            if (lane < 2)
                hW[ee*HSTR + lane+64] = silu_f(pa2 + Pb[lane+64] + rd*rw2);
        }
        __syncwarp();

        // ---- phase 2: m[e][4q..4q+3] = silu(h[e] @ W2 + b2) * mask  (f32x2)
        {
            const ulonglong2* w2p = (const ulonglong2*)s_W2;   // row n at n*4, lane chunk +q
            const float4* h4 = (const float4*)&hW[e*HSTR];
            ull acc01 = pack2(s_b2[4*q],   s_b2[4*q+1]);
            ull acc23 = pack2(s_b2[4*q+2], s_b2[4*q+3]);
#pragma unroll
            for (int g = 0; g < 16; g++) {
                float4 hh = h4[g];
                ulonglong2 wv0 = w2p[(4*g+0)*4 + q];
                ull hp = pack2(hh.x, hh.x);
                fma2(acc01, hp, wv0.x); fma2(acc23, hp, wv0.y);
                ulonglong2 wv1 = w2p[(4*g+1)*4 + q];
                hp = pack2(hh.y, hh.y);
                fma2(acc01, hp, wv1.x); fma2(acc23, hp, wv1.y);
                ulonglong2 wv2 = w2p[(4*g+2)*4 + q];
                hp = pack2(hh.z, hh.z);
                fma2(acc01, hp, wv2.x); fma2(acc23, hp, wv2.y);
                ulonglong2 wv3 = w2p[(4*g+3)*4 + q];
                hp = pack2(hh.w, hh.w);
                fma2(acc01, hp, wv3.x); fma2(acc23, hp, wv3.y);
            }
            float h64 = hW[e*HSTR + 64], h65 = hW[e*HSTR + 65];
            ulonglong2 wv64 = w2p[64*4 + q];
            ull hp = pack2(h64, h64);
            fma2(acc01, hp, wv64.x); fma2(acc23, hp, wv64.y);
            ulonglong2 wv65 = w2p[65*4 + q];
            hp = pack2(h65, h65);
            fma2(acc01, hp, wv65.x); fma2(acc23, hp, wv65.y);

            float2 a01 = unpack2(acc01), a23 = unpack2(acc23);
            float me = __shfl_sync(0xffffffffu, maskf, e);
            float4 mv;
            mv.x = silu_f(a01.x) * me;
            mv.y = silu_f(a01.y) * me;
            mv.z = silu_f(a23.x) * me;
            mv.w = silu_f(a23.y) * me;
            *(float4*)&mW[e*MSTR + 4*q] = mv;

            mi4 = mv;
#pragma unroll
            for (int off = 4; off <= 16; off <<= 1) {
                mi4.x += __shfl_xor_sync(0xffffffffu, mi4.x, off);
                mi4.y += __shfl_xor_sync(0xffffffffu, mi4.y, off);
                mi4.z += __shfl_xor_sync(0xffffffffu, mi4.z, off);
                mi4.w += __shfl_xor_sync(0xffffffffu, mi4.w, off);
            }
        }
        __syncwarp();

        // ---- phase 3: coors MLP (f32x2); lane (e,q) handles u = 4t+q
        {
            const float4* m4 = (const float4*)&mW[e*MSTR];
            float4 mr0 = m4[0], mr1 = m4[1], mr2 = m4[2], mr3 = m4[3];
            ull mp0 = pack2(mr0.x, mr0.y), mp1 = pack2(mr0.z, mr0.w);
            ull mp2 = pack2(mr1.x, mr1.y), mp3 = pack2(mr1.z, mr1.w);
            ull mp4 = pack2(mr2.x, mr2.y), mp5 = pack2(mr2.z, mr2.w);
            ull mp6 = pack2(mr3.x, mr3.y), mp7 = pack2(mr3.z, mr3.w);
            const ulonglong2* cwp = (const ulonglong2*)s_cW1T;   // row u at u*5
            float wacc = 0.0f;
#pragma unroll
            for (int t = 0; t < 16; t++) {
                int u = 4*t + q;
                ulonglong2 w0 = cwp[u*5+0];
                ulonglong2 w1 = cwp[u*5+1];
                ulonglong2 w4 = cwp[u*5+4];          // (cb1[u], cW2[u], pad, pad)
                float2 cc = unpack2(w4.x);
                ull s01 = pack2(cc.x, 0.0f);
                fma2(s01, mp0, w0.x); fma2(s01, mp1, w0.y);
                fma2(s01, mp2, w1.x); fma2(s01, mp3, w1.y);
                ulonglong2 w2v = cwp[u*5+2];
                ulonglong2 w3 = cwp[u*5+3];
                fma2(s01, mp4, w2v.x); fma2(s01, mp5, w2v.y);
                fma2(s01, mp6, w3.x);  fma2(s01, mp7, w3.y);
                float2 sv = unpack2(s01);
                wacc += silu_f(sv.x + sv.y) * cc.y;
            }
            wacc += __shfl_xor_sync(0xffffffffu, wacc, 1);
            wacc += __shfl_xor_sync(0xffffffffu, wacc, 2);
            float wk = (__shfl_sync(0xffffffffu, wacc, 4*kk) + s_cb2) * maskf;
            float tx = wk*dxk, ty = wk*dyk, tz = wk*dzk;
#pragma unroll
            for (int off = 1; off <= 4; off <<= 1) {
                tx += __shfl_xor_sync(0xffffffffu, tx, off);
                ty += __shfl_xor_sync(0xffffffffu, ty, off);
                tz += __shfl_xor_sync(0xffffffffu, tz, off);
            }
            ax = tx; ay = ty; az = tz;
        }
    }

    if (lane == 0) {
        coorsOut[row*3+0] = cix + ax;
        coorsOut[row*3+1] = ciy + ay;
        coorsOut[row*3+2] = ciz + az;
    }

    // ---- phase 4: LayerNorm + node MLP (all rows)
    float s = fcv;
#pragma unroll
    for (int off = 8; off > 0; off >>= 1) s += __shfl_xor_sync(0xffffffffu, s, off);
    float mu = s * (1.0f/16.0f);
    float dv = fcv - mu;
    float v = dv*dv;
#pragma unroll
    for (int off = 8; off > 0; off >>= 1) v += __shfl_xor_sync(0xffffffffu, v, off);
    float var = v * (1.0f/16.0f);
    float normed = dv * rsqrtf(var + 1e-5f) * s_g[c] + s_bta[c];

    if (half == 0) s_nin[w][c] = normed;
    if (lane < 4)  *(float4*)&s_nin[w][16 + 4*q] = mi4;
    __syncwarp();

    {
        const ulonglong2* nin2 = (const ulonglong2*)&s_nin[w][0];
        const ulonglong2* w1r2 = (const ulonglong2*)&s_nW1T[lane][0];
        ull acc = pack2(s_nb1[lane], 0.0f);
#pragma unroll
        for (int g = 0; g < 8; g++) {
            ulonglong2 nv = nin2[g];
            ulonglong2 wv = w1r2[g];
            fma2(acc, nv.x, wv.x);
            fma2(acc, nv.y, wv.y);
        }
        float2 av = unpack2(acc);
        s_hid[w][lane] = silu_f(av.x + av.y);
    }
    __syncwarp();

    {
        const float4* hid4 = (const float4*)&s_hid[w][16*half];
        const float4* w2r  = (const float4*)&s_nW2T[c][16*half];
        float o = 0.0f;
#pragma unroll
        for (int g2 = 0; g2 < 4; g2++) o += dot4(hid4[g2], w2r[g2]);
        o += __shfl_xor_sync(0xffffffffu, o, 16);
        if (half == 0)
            featsOut[row*DD + c] = fcv + o + s_nb2[c];
    }
}

// ---------------- final projection: delta = feats @ final_w + final_b
__global__ void k_final(const float* __restrict__ fw, const float* __restrict__ fb, float* __restrict__ out){
    int t = blockIdx.x*blockDim.x + threadIdx.x;
    if (t >= BB*LL) return;
    const float* f = &g_feats[1][t*DD];   // after 3 layers, feats live in buffer 1
    float o0 = fb[0], o1 = fb[1], o2 = fb[2];
#pragma unroll
    for (int c2 = 0; c2 < DD; c2++){
        float fc = f[c2];
        o0 += fc * fw[c2*3+0];
        o1 += fc * fw[c2*3+1];
        o2 += fc * fw[c2*3+2];
    }
    out[t*3+0] = o0; out[t*3+1] = o1; out[t*3+2] = o2;
}

extern "C" void kernel_launch(void* const* d_in, const int* in_sizes, int n_in,
                              void* d_out, int out_size){
    int I_coords=0, I_res=1, I_len=2, I_tok=3, I_pos=4,
        I_ew1=5, I_eb1=6, I_ew2=7, I_eb2=8,
        I_cw1=9, I_cb1=10, I_cw2=11, I_cb2=12,
        I_lng=13, I_lnb=14, I_nw1=15, I_nb1=16, I_nw2=17, I_nb2=18,
        I_fw=19, I_fb=20;
    if (n_in >= 21 && in_sizes[1] == 192) {
        I_coords=0; I_cb1=1; I_cb2=2; I_cw1=3; I_cw2=4;
        I_eb1=5; I_eb2=6; I_ew1=7; I_ew2=8; I_fb=9; I_fw=10; I_len=11;
        I_lnb=12; I_lng=13; I_nb1=14; I_nb2=15; I_nw1=16; I_nw2=17;
        I_pos=18; I_res=19; I_tok=20;
    }

    const float* coords   = (const float*)d_in[I_coords];
    const int*   residues = (const int*)  d_in[I_res];
    const int*   lengths  = (const int*)  d_in[I_len];
    const float* tok      = (const float*)d_in[I_tok];
    const float* pos      = (const float*)d_in[I_pos];
    const float* ew1      = (const float*)d_in[I_ew1];
    const float* eb1      = (const float*)d_in[I_eb1];
    const float* ew2      = (const float*)d_in[I_ew2];
    const float* eb2      = (const float*)d_in[I_eb2];
    const float* cw1      = (const float*)d_in[I_cw1];
    const float* cb1      = (const float*)d_in[I_cb1];
    const float* cw2      = (const float*)d_in[I_cw2];
    const float* cb2      = (const float*)d_in[I_cb2];
    const float* lng      = (const float*)d_in[I_lng];
    const float* lnb      = (const float*)d_in[I_lnb];
    const float* nw1      = (const float*)d_in[I_nw1];
    const float* nb1      = (const float*)d_in[I_nb1];
    const float* nw2      = (const float*)d_in[I_nw2];
    const float* nb2      = (const float*)d_in[I_nb2];
    const float* fw       = (const float*)d_in[I_fw];
    const float* fb       = (const float*)d_in[I_fb];
    float* out = (float*)d_out;

    k_init<<<64, 256>>>(coords, residues, tok, pos, lengths);
    for (int dd = 0; dd < 3; dd++){
        int bin = dd & 1;
        k_knnpre<<<768, 256>>>(bin, lengths, ew1, eb1, dd);
        k_layer<<<BB*LL/8, 256>>>(bin, dd, lengths, ew1, ew2, eb2,
                                  cw1, cb1, cw2, cb2, lng, lnb,
                                  nw1, nb1, nw2, nb2);
    }
    k_final<<<64, 256>>>(fw, fb, out);
}